// round 13
// baseline (speedup 1.0000x reference)
#include <cuda_runtime.h>
#include <cuda_bf16.h>
#include <cuda_fp16.h>
#include <cstdint>

#define NMAX 100000
#define EMAX 1600000
#define HID 128
#define HEADS 8
#define NLAYERS 6
#define LOG2E 1.44269504f

// ---------------- scratch (device globals; no allocation allowed) ----------------
__device__ __align__(16) float g_hA[(size_t)NMAX * HID];
__device__ __align__(16) float g_hB[(size_t)NMAX * HID];
__device__ __align__(16) __half g_hp16[(size_t)NMAX * HID];    // fp16 messages
__device__ __align__(16) __half g_as16[(size_t)NMAX * HEADS];  // fp16 alpha_src (x log2e)
__device__ __align__(16) float g_ad[(size_t)NMAX * HEADS];     // fp32 alpha_dst (x log2e)
__device__ int g_off[NMAX + 1];
__device__ int g_deg[NMAX];
__device__ int g_cnt[NMAX];
__device__ int g_bsum[256];
__device__ int g_eid[EMAX];
__device__ int g_srcS[EMAX];
__device__ __align__(8) uint2 g_eaS2[EMAX];  // half4 edge attrs, dst-sorted
__device__ float g_weh[NLAYERS * 4 * HEADS]; // x log2e
// degree-sorted node schedule
__device__ int g_hcnt[256];
__device__ int g_hcnt2[256];
__device__ int g_hoff[257];
__device__ int g_perm[NMAX];
// pre-split transposed weights: [7][n=128][k=128] bf16 (6 GAT layers + W1)
__device__ __align__(16) __nv_bfloat16 g_Bh[7 * 128 * 128];
__device__ __align__(16) __nv_bfloat16 g_Bl[7 * 128 * 128];

// ---------------- utils ----------------
__device__ __forceinline__ float warp_sum(float v) {
#pragma unroll
    for (int o = 16; o; o >>= 1) v += __shfl_xor_sync(0xffffffffu, v, o);
    return v;
}

__device__ __forceinline__ float ex2(float x) {
    float y;
    asm("ex2.approx.ftz.f32 %0, %1;" : "=f"(y) : "f"(x));
    return y;
}

__device__ __forceinline__ uint32_t smem_u32(const void* p) {
    uint32_t a;
    asm("{ .reg .u64 t; cvta.to.shared.u64 t, %1; cvt.u32.u64 %0, t; }" : "=r"(a) : "l"(p));
    return a;
}

__device__ __forceinline__ void mma16816(float* d, uint32_t a0, uint32_t a1, uint32_t a2,
                                         uint32_t a3, uint32_t b0, uint32_t b1) {
    asm volatile(
        "mma.sync.aligned.m16n8k16.row.col.f32.bf16.bf16.f32 "
        "{%0,%1,%2,%3}, {%4,%5,%6,%7}, {%8,%9}, {%0,%1,%2,%3};"
        : "+f"(d[0]), "+f"(d[1]), "+f"(d[2]), "+f"(d[3])
        : "r"(a0), "r"(a1), "r"(a2), "r"(a3), "r"(b0), "r"(b1));
}

__device__ __forceinline__ void ldsm_x4(uint32_t& r0, uint32_t& r1, uint32_t& r2, uint32_t& r3,
                                        uint32_t addr) {
    asm volatile("ldmatrix.sync.aligned.m8n8.x4.shared.b16 {%0,%1,%2,%3}, [%4];"
                 : "=r"(r0), "=r"(r1), "=r"(r2), "=r"(r3) : "r"(addr));
}

// ---------------- preprocessing ----------------
__global__ void k_zero(int n) {
    int i = blockIdx.x * blockDim.x + threadIdx.x;
    if (i < n) { g_deg[i] = 0; g_cnt[i] = 0; }
    if (i < 256) { g_hcnt[i] = 0; g_hcnt2[i] = 0; }
}

__global__ void k_hist(const int* __restrict__ ei, int Ee) {
    int e = blockIdx.x * blockDim.x + threadIdx.x;
    if (e < Ee) atomicAdd(&g_deg[ei[Ee + e]], 1);
}

__global__ void k_scan1(int n) {
    __shared__ int ws[32];
    int i = blockIdx.x * 1024 + threadIdx.x;
    int lane = threadIdx.x & 31, wid = threadIdx.x >> 5;
    int v = (i < n) ? g_deg[i] : 0;
    int x = v;
#pragma unroll
    for (int o = 1; o < 32; o <<= 1) {
        int y = __shfl_up_sync(0xffffffffu, x, o);
        if (lane >= o) x += y;
    }
    if (lane == 31) ws[wid] = x;
    __syncthreads();
    if (wid == 0) {
        int y = ws[lane];
#pragma unroll
        for (int o = 1; o < 32; o <<= 1) {
            int z = __shfl_up_sync(0xffffffffu, y, o);
            if (lane >= o) y += z;
        }
        ws[lane] = y;
    }
    __syncthreads();
    int inc = x + (wid > 0 ? ws[wid - 1] : 0);
    if (i < n) g_off[i] = inc - v;
    if (threadIdx.x == 1023) g_bsum[blockIdx.x] = inc;
}

__global__ void k_scan2(int nb) {
    int lane = threadIdx.x;  // 32 threads
    int run = 0;
    for (int base = 0; base < nb; base += 32) {
        int idx = base + lane;
        int v = (idx < nb) ? g_bsum[idx] : 0;
        int x = v;
#pragma unroll
        for (int o = 1; o < 32; o <<= 1) {
            int y = __shfl_up_sync(0xffffffffu, x, o);
            if (lane >= o) x += y;
        }
        if (idx < nb) g_bsum[idx] = x - v + run;
        run += __shfl_sync(0xffffffffu, x, 31);
    }
    if (lane == 0) g_bsum[nb] = run;
}

__global__ void k_scan3(int n) {
    int i = blockIdx.x * 1024 + threadIdx.x;
    if (i < n) g_off[i] += g_bsum[blockIdx.x];
    if (i == 0) g_off[n] = g_bsum[gridDim.x];
}

__global__ void k_scatter(const int* __restrict__ ei, int Ee) {
    int e = blockIdx.x * blockDim.x + threadIdx.x;
    if (e >= Ee) return;
    int d = ei[Ee + e];
    int p = g_off[d] + atomicAdd(&g_cnt[d], 1);
    g_eid[p] = e;
}

// ---- degree-sorted schedule: histogram over (255 - clamped degree) = descending ----
__global__ void k_dhist(int Nn) {
    int n = blockIdx.x * blockDim.x + threadIdx.x;
    if (n >= Nn) return;
    int b = 255 - min(g_deg[n], 255);
    atomicAdd(&g_hcnt[b], 1);
}

__global__ void k_dscan() {
    int lane = threadIdx.x;  // 32 threads
    int run = 0;
    for (int base = 0; base < 256; base += 32) {
        int idx = base + lane;
        int v = g_hcnt[idx];
        int x = v;
#pragma unroll
        for (int o = 1; o < 32; o <<= 1) {
            int y = __shfl_up_sync(0xffffffffu, x, o);
            if (lane >= o) x += y;
        }
        g_hoff[idx] = x - v + run;
        run += __shfl_sync(0xffffffffu, x, 31);
    }
    if (lane == 0) g_hoff[256] = run;
}

__global__ void k_dscatter(int Nn) {
    int n = blockIdx.x * blockDim.x + threadIdx.x;
    if (n >= Nn) return;
    int b = 255 - min(g_deg[n], 255);
    int pos = g_hoff[b] + atomicAdd(&g_hcnt2[b], 1);
    g_perm[pos] = n;
}

__device__ __forceinline__ uint2 pack_half4(float4 v) {
    __half2 p0 = __floats2half2_rn(v.x, v.y);
    __half2 p1 = __floats2half2_rn(v.z, v.w);
    uint2 u;
    u.x = *reinterpret_cast<uint32_t*>(&p0);
    u.y = *reinterpret_cast<uint32_t*>(&p1);
    return u;
}

__global__ void k_sortfix(const int* __restrict__ ei, const float4* __restrict__ ea, int Nn) {
    int n = blockIdx.x * blockDim.x + threadIdx.x;
    if (n >= Nn) return;
    int st = g_off[n], en = g_off[n + 1];
    int d = en - st;
    if (d <= 0) return;
    if (d <= 192) {
        int a[192];
        for (int i = 0; i < d; i++) a[i] = g_eid[st + i];
        for (int i = 1; i < d; i++) {
            int key = a[i]; int j = i - 1;
            while (j >= 0 && a[j] > key) { a[j + 1] = a[j]; j--; }
            a[j + 1] = key;
        }
        for (int i = 0; i < d; i++) {
            int eid = a[i];
            g_srcS[st + i] = ei[eid];
            g_eaS2[st + i] = pack_half4(ea[eid]);
        }
    } else {
        for (int i = 0; i < d - 1; i++) {
            int mn = i;
            for (int j = i + 1; j < d; j++)
                if (g_eid[st + j] < g_eid[st + mn]) mn = j;
            int t = g_eid[st + i]; g_eid[st + i] = g_eid[st + mn]; g_eid[st + mn] = t;
        }
        for (int i = 0; i < d; i++) {
            int eid = g_eid[st + i];
            g_srcS[st + i] = ei[eid];
            g_eaS2[st + i] = pack_half4(ea[eid]);
        }
    }
}

// edge attention weights folded per layer (x log2e)
__global__ void k_prep_weh(const float* __restrict__ We, const float* __restrict__ aev) {
    int l = blockIdx.x;
    int t = threadIdx.x;  // 32
    int d = t >> 3, h = t & 7;
    float s = 0.f;
#pragma unroll
    for (int c = 0; c < 16; c++)
        s += We[l * 4 * HID + d * HID + h * 16 + c] * aev[l * HID + h * 16 + c];
    g_weh[l * 32 + d * 8 + h] = s * LOG2E;
}

// transpose + bf16-split weights
__global__ void k_prep_bsplit(const float* __restrict__ Wg, const float* __restrict__ W1) {
    int l = blockIdx.x;
    const float* W = (l < NLAYERS) ? (Wg + (size_t)l * HID * HID) : W1;
    int n = threadIdx.x;
    __nv_bfloat16* bh = g_Bh + (size_t)l * HID * HID;
    __nv_bfloat16* bl = g_Bl + (size_t)l * HID * HID;
    for (int k = 0; k < HID; k++) {
        float v = W[k * HID + n];
        __nv_bfloat16 hb = __float2bfloat16(v);
        float r = v - __bfloat162float(hb);
        bh[n * HID + k] = hb;
        bl[n * HID + k] = __float2bfloat16(r);
    }
}

// ---------------- input projection: h0 = LN(relu(x @ W_in + b_in)) ----------------
__global__ void k_input(const float* __restrict__ x, const float* __restrict__ Win,
                        const float* __restrict__ bin, const float* __restrict__ g,
                        const float* __restrict__ b, float* __restrict__ h0, int Nn) {
    __shared__ float Ws[16 * HID];
    for (int i = threadIdx.x; i < 16 * HID; i += blockDim.x) Ws[i] = Win[i];
    __syncthreads();
    int gw = (blockIdx.x * blockDim.x + threadIdx.x) >> 5;
    if (gw >= Nn) return;
    int lane = threadIdx.x & 31;
    float4 bv = ((const float4*)bin)[lane];
    float acc0 = bv.x, acc1 = bv.y, acc2 = bv.z, acc3 = bv.w;
#pragma unroll
    for (int k = 0; k < 16; k++) {
        float xv = __ldg(x + (size_t)gw * 16 + k);
        acc0 += xv * Ws[k * HID + lane * 4 + 0];
        acc1 += xv * Ws[k * HID + lane * 4 + 1];
        acc2 += xv * Ws[k * HID + lane * 4 + 2];
        acc3 += xv * Ws[k * HID + lane * 4 + 3];
    }
    float t0 = fmaxf(acc0, 0.f), t1 = fmaxf(acc1, 0.f), t2 = fmaxf(acc2, 0.f), t3 = fmaxf(acc3, 0.f);
    float sm = warp_sum(t0 + t1 + t2 + t3);
    float sq = warp_sum(t0 * t0 + t1 * t1 + t2 * t2 + t3 * t3);
    float mu = sm * (1.f / 128.f);
    float var = sq * (1.f / 128.f) - mu * mu;
    float rs = rsqrtf(var + 1e-5f);
    float4 gv = ((const float4*)g)[lane];
    float4 bbv = ((const float4*)b)[lane];
    float4 o;
    o.x = (t0 - mu) * rs * gv.x + bbv.x;
    o.y = (t1 - mu) * rs * gv.y + bbv.y;
    o.z = (t2 - mu) * rs * gv.z + bbv.z;
    o.w = (t3 - mu) * rs * gv.w + bbv.w;
    ((float4*)(h0 + (size_t)gw * HID))[lane] = o;
}

// ---------------- HMMA GEMM: C[M,128] = A[M,128] @ W[128,128] via bf16x3 split ----
// M-tile 64 (2 CTAs/SM), warp layout 2(M) x 4(N). Fragments via ldmatrix.x4.
// MODE 0: C -> fp16 hp, fused fp16 alpha_src + fp32 alpha_dst epilogue (x log2e)
// MODE 1: fused output head: out = relu(relu(C + b1) @ W2 + b2), OUT_DIM=3
#define RS 272
#define OFF_AHI 0
#define OFF_ALO 17408
#define OFF_BHI 34816
#define OFF_BLO 69632
#define OFF_ATT 104448
#define SM_TOT  105472

template <int MODE>
__global__ void __launch_bounds__(256, 2) k_mma(
    const float* __restrict__ A, const __nv_bfloat16* __restrict__ BhG,
    const __nv_bfloat16* __restrict__ BlG, const float* __restrict__ v1,
    const float* __restrict__ v2, __half* __restrict__ Ch,
    __half* __restrict__ oAS, float* __restrict__ oAD,
    const float* __restrict__ W2g, const float* __restrict__ b2g,
    float* __restrict__ outg, int M) {
    extern __shared__ char smem[];
    char* Ahi = smem + OFF_AHI;
    char* Alo = smem + OFF_ALO;
    char* Bhi = smem + OFF_BHI;
    char* Blo = smem + OFF_BLO;
    float* att = (float*)(smem + OFF_ATT);
    float* Cs = (float*)smem;  // reused after compute (row stride 132 floats)
    const int tid = threadIdx.x;
    const int m0 = blockIdx.x * 64;

    if (MODE == 0) {
        if (tid < 128) att[tid] = v1[tid] * LOG2E;
        else att[tid] = v2[tid - 128] * LOG2E;
    } else {
        if (tid < 128) att[tid] = v1[tid];
    }

    // ---- fill A (64 rows): fp32 -> bf16 hi/lo ----
#pragma unroll
    for (int it = 0; it < 4; it++) {
        int q = tid + it * 256;
        int r = q >> 4, w = q & 15;
        int m = m0 + r;
        float f[8];
        if (m < M) {
            const float* ar = A + (size_t)m * HID + w * 8;
            float4 x0 = *(const float4*)ar;
            float4 x1 = *(const float4*)(ar + 4);
            f[0] = x0.x; f[1] = x0.y; f[2] = x0.z; f[3] = x0.w;
            f[4] = x1.x; f[5] = x1.y; f[6] = x1.z; f[7] = x1.w;
        } else {
#pragma unroll
            for (int i = 0; i < 8; i++) f[i] = 0.f;
        }
        uint32_t hu[8], lu[8];
#pragma unroll
        for (int i = 0; i < 8; i++) {
            __nv_bfloat16 hb = __float2bfloat16(f[i]);
            float rr = f[i] - __bfloat162float(hb);
            hu[i] = (uint32_t)__bfloat16_as_ushort(hb);
            lu[i] = (uint32_t)__bfloat16_as_ushort(__float2bfloat16(rr));
        }
        uint4 ph, pl;
        ph.x = hu[0] | (hu[1] << 16); ph.y = hu[2] | (hu[3] << 16);
        ph.z = hu[4] | (hu[5] << 16); ph.w = hu[6] | (hu[7] << 16);
        pl.x = lu[0] | (lu[1] << 16); pl.y = lu[2] | (lu[3] << 16);
        pl.z = lu[4] | (lu[5] << 16); pl.w = lu[6] | (lu[7] << 16);
        *(uint4*)(Ahi + r * RS + w * 16) = ph;
        *(uint4*)(Alo + r * RS + w * 16) = pl;
    }
    // ---- fill B (pre-split bf16 [n][k], 256B rows, 128 rows) ----
#pragma unroll
    for (int it = 0; it < 8; it++) {
        int q = tid + it * 256;
        int r = q >> 4, w = q & 15;
        *(uint4*)(Bhi + r * RS + w * 16) = *(const uint4*)((const char*)BhG + r * 256 + w * 16);
        *(uint4*)(Blo + r * RS + w * 16) = *(const uint4*)((const char*)BlG + r * 256 + w * 16);
    }
    __syncthreads();

    const int wid = tid >> 5, lane = tid & 31;
    const int cq = lane & 3, gq = lane >> 2;
    const int mb = (wid & 1) * 32;
    const int nb = (wid >> 1) * 32;

    float acc[2][4][4];
#pragma unroll
    for (int a = 0; a < 2; a++)
#pragma unroll
        for (int j = 0; j < 4; j++)
#pragma unroll
            for (int i = 0; i < 4; i++) acc[a][j][i] = 0.f;

    const uint32_t sbase = smem_u32(smem);
    const int l7 = lane & 7;
    const uint32_t aAddr = sbase + OFF_AHI +
        (uint32_t)(mb + l7 + ((lane >> 3) & 1) * 8) * RS + ((lane >> 4) & 1) * 16;
    const uint32_t bAddr = sbase + OFF_BHI +
        (uint32_t)(nb + ((lane >> 4) & 1) * 8 + l7) * RS + ((lane >> 3) & 1) * 16;
    const uint32_t ALO_D = OFF_ALO - OFF_AHI;
    const uint32_t BLO_D = OFF_BLO - OFF_BHI;

#pragma unroll
    for (int kc = 0; kc < 8; kc++) {
        const uint32_t kby = kc * 32;
        uint32_t ah[2][4], al[2][4], bh[4][2], bl[4][2];
        ldsm_x4(ah[0][0], ah[0][1], ah[0][2], ah[0][3], aAddr + kby);
        ldsm_x4(ah[1][0], ah[1][1], ah[1][2], ah[1][3], aAddr + 16 * RS + kby);
        ldsm_x4(al[0][0], al[0][1], al[0][2], al[0][3], aAddr + ALO_D + kby);
        ldsm_x4(al[1][0], al[1][1], al[1][2], al[1][3], aAddr + ALO_D + 16 * RS + kby);
        ldsm_x4(bh[0][0], bh[0][1], bh[1][0], bh[1][1], bAddr + kby);
        ldsm_x4(bh[2][0], bh[2][1], bh[3][0], bh[3][1], bAddr + 16 * RS + kby);
        ldsm_x4(bl[0][0], bl[0][1], bl[1][0], bl[1][1], bAddr + BLO_D + kby);
        ldsm_x4(bl[2][0], bl[2][1], bl[3][0], bl[3][1], bAddr + BLO_D + 16 * RS + kby);
#pragma unroll
        for (int j = 0; j < 4; j++) {
#pragma unroll
            for (int mt = 0; mt < 2; mt++) {
                mma16816(acc[mt][j], ah[mt][0], ah[mt][1], ah[mt][2], ah[mt][3],
                         bh[j][0], bh[j][1]);
                mma16816(acc[mt][j], al[mt][0], al[mt][1], al[mt][2], al[mt][3],
                         bh[j][0], bh[j][1]);
                mma16816(acc[mt][j], ah[mt][0], ah[mt][1], ah[mt][2], ah[mt][3],
                         bl[j][0], bl[j][1]);
            }
        }
    }

    // ---- fused alpha epilogue (MODE 0): alpha_src -> fp16, alpha_dst -> fp32 ----
    if (MODE == 0) {
        float sAS[2][2][2], sAD[2][2][2];
#pragma unroll
        for (int a = 0; a < 2; a++)
#pragma unroll
            for (int hf = 0; hf < 2; hf++)
#pragma unroll
                for (int h = 0; h < 2; h++) { sAS[a][hf][h] = 0.f; sAD[a][hf][h] = 0.f; }
#pragma unroll
        for (int mt = 0; mt < 2; mt++)
#pragma unroll
            for (int j = 0; j < 4; j++) {
                int hl = j >> 1;
                int col = nb + j * 8 + 2 * cq;
                float w0 = att[col], w1 = att[col + 1];
                float u0 = att[128 + col], u1 = att[128 + col + 1];
                sAS[mt][0][hl] += acc[mt][j][0] * w0 + acc[mt][j][1] * w1;
                sAS[mt][1][hl] += acc[mt][j][2] * w0 + acc[mt][j][3] * w1;
                sAD[mt][0][hl] += acc[mt][j][0] * u0 + acc[mt][j][1] * u1;
                sAD[mt][1][hl] += acc[mt][j][2] * u0 + acc[mt][j][3] * u1;
            }
#pragma unroll
        for (int mt = 0; mt < 2; mt++)
#pragma unroll
            for (int hf = 0; hf < 2; hf++)
#pragma unroll
                for (int h = 0; h < 2; h++) {
                    float v = sAS[mt][hf][h];
                    v += __shfl_xor_sync(0xffffffffu, v, 1);
                    v += __shfl_xor_sync(0xffffffffu, v, 2);
                    sAS[mt][hf][h] = v;
                    float u = sAD[mt][hf][h];
                    u += __shfl_xor_sync(0xffffffffu, u, 1);
                    u += __shfl_xor_sync(0xffffffffu, u, 2);
                    sAD[mt][hf][h] = u;
                }
        if (cq == 0) {
#pragma unroll
            for (int mt = 0; mt < 2; mt++)
#pragma unroll
                for (int hf = 0; hf < 2; hf++) {
                    int r = m0 + mb + mt * 16 + hf * 8 + gq;
                    if (r < M) {
                        __half2 p = __floats2half2_rn(sAS[mt][hf][0], sAS[mt][hf][1]);
                        *(uint32_t*)(oAS + (size_t)r * 8 + (nb >> 4)) =
                            *reinterpret_cast<uint32_t*>(&p);
                        *(float2*)(oAD + (size_t)r * 8 + (nb >> 4)) =
                            make_float2(sAD[mt][hf][0], sAD[mt][hf][1]);
                    }
                }
        }
    }

    // ---- stage C in SMEM ----
    __syncthreads();
#pragma unroll
    for (int mt = 0; mt < 2; mt++)
#pragma unroll
        for (int j = 0; j < 4; j++) {
            int row = mb + mt * 16 + gq;
            int col = nb + j * 8 + 2 * cq;
            *(float2*)(Cs + row * 132 + col) = make_float2(acc[mt][j][0], acc[mt][j][1]);
            *(float2*)(Cs + (row + 8) * 132 + col) = make_float2(acc[mt][j][2], acc[mt][j][3]);
        }
    __syncthreads();

    if (MODE == 0) {
        // write hp as fp16, coalesced
#pragma unroll
        for (int it = 0; it < 8; it++) {
            int q = tid + it * 256;
            int r = q >> 5, w = q & 31;
            int m = m0 + r;
            if (m < M) {
                float4 v = *(float4*)(Cs + r * 132 + w * 4);
                __half2 p0 = __floats2half2_rn(v.x, v.y);
                __half2 p1 = __floats2half2_rn(v.z, v.w);
                uint2 u;
                u.x = *reinterpret_cast<uint32_t*>(&p0);
                u.y = *reinterpret_cast<uint32_t*>(&p1);
                *(uint2*)(Ch + (size_t)m * HID + w * 4) = u;
            }
        }
    } else {
        // fused output head: out[m] = relu( relu(C[m]+b1) @ W2 + b2 ), OUT_DIM=3
        int r = tid >> 2;       // row 0..63
        int qq = tid & 3;       // channel quarter
        int m = m0 + r;
        float p0 = 0.f, p1 = 0.f, p2 = 0.f;
        const float* cr = Cs + r * 132 + qq * 32;
        const float* ar = att + qq * 32;
        const float* w2 = W2g + qq * 32 * 3;
#pragma unroll
        for (int i = 0; i < 32; i++) {
            float v = fmaxf(cr[i] + ar[i], 0.f);
            p0 = fmaf(v, __ldg(&w2[i * 3 + 0]), p0);
            p1 = fmaf(v, __ldg(&w2[i * 3 + 1]), p1);
            p2 = fmaf(v, __ldg(&w2[i * 3 + 2]), p2);
        }
        p0 += __shfl_xor_sync(0xffffffffu, p0, 1);
        p0 += __shfl_xor_sync(0xffffffffu, p0, 2);
        p1 += __shfl_xor_sync(0xffffffffu, p1, 1);
        p1 += __shfl_xor_sync(0xffffffffu, p1, 2);
        p2 += __shfl_xor_sync(0xffffffffu, p2, 1);
        p2 += __shfl_xor_sync(0xffffffffu, p2, 2);
        if (qq == 0 && m < M) {
            outg[(size_t)m * 3 + 0] = fmaxf(p0 + __ldg(&b2g[0]), 0.f);
            outg[(size_t)m * 3 + 1] = fmaxf(p1 + __ldg(&b2g[1]), 0.f);
            outg[(size_t)m * 3 + 2] = fmaxf(p2 + __ldg(&b2g[2]), 0.f);
        }
    }
}

// ---------------- fused attention + aggregation + residual + LN (R7 champion) ----
// Half-warp per edge; each lane covers 8 channels; 1-ahead (src,ea) prefetch.
// Node assignment via degree-sorted permutation for load balance.
__global__ void k_gat_edge(const float* __restrict__ hcur, const float* __restrict__ weh_l,
                           const float* __restrict__ bgl, const float* __restrict__ lng,
                           const float* __restrict__ lnb, float* __restrict__ hnext, int Nn) {
    int wgl = (blockIdx.x * blockDim.x + threadIdx.x) >> 5;
    if (wgl >= Nn) return;
    int gw = g_perm[wgl];
    int lane = threadIdx.x & 31;
    int half = lane >> 4;
    int sl = lane & 15;      // channel group: 8*sl .. 8*sl+7
    int hh = sl >> 1;        // head
    float adv = __ldg(&g_ad[(size_t)gw * 8 + hh]);
    float w0 = __ldg(&weh_l[0 * 8 + hh]);
    float w1 = __ldg(&weh_l[1 * 8 + hh]);
    float w2 = __ldg(&weh_l[2 * 8 + hh]);
    float w3 = __ldg(&weh_l[3 * 8 + hh]);
    int s0 = g_off[gw], s1 = g_off[gw + 1];
    int d = s1 - s0;

    float acc[8];
#pragma unroll
    for (int q = 0; q < 8; q++) acc[q] = 0.f;
    float den = 0.f;

    int i = half;
    int sP = 0; uint2 eaP = make_uint2(0, 0);
    if (i < d) { sP = __ldg(&g_srcS[s0 + i]); eaP = g_eaS2[s0 + i]; }
    for (; i < d; i += 2) {
        int s = sP; uint2 eau = eaP;
        if (i + 2 < d) { sP = __ldg(&g_srcS[s0 + i + 2]); eaP = g_eaS2[s0 + i + 2]; }
        float asv = __half2float(g_as16[(size_t)s * 8 + hh]);
        float2 f01 = __half22float2(*reinterpret_cast<__half2*>(&eau.x));
        float2 f23 = __half22float2(*reinterpret_cast<__half2*>(&eau.y));
        float al = asv + adv + f01.x * w0 + f01.y * w1 + f23.x * w2 + f23.y * w3;
        al = fmaxf(al, 0.2f * al);
        float a = ex2(al);
        den += a;
        uint4 hv = *(const uint4*)(g_hp16 + (size_t)s * HID + sl * 8);
        __half2* hp2 = reinterpret_cast<__half2*>(&hv);
#pragma unroll
        for (int q = 0; q < 4; q++) {
            float2 f = __half22float2(hp2[q]);
            acc[2 * q] = fmaf(a, f.x, acc[2 * q]);
            acc[2 * q + 1] = fmaf(a, f.y, acc[2 * q + 1]);
        }
    }

    // merge even/odd halves (fixed order)
#pragma unroll
    for (int q = 0; q < 8; q++) acc[q] += __shfl_xor_sync(0xffffffffu, acc[q], 16);
    den += __shfl_xor_sync(0xffffffffu, den, 16);

    float r = 1.f / (den + 1e-16f);
    const float4* hcr = (const float4*)(hcur + (size_t)gw * HID + sl * 8);
    float4 hc0 = hcr[0], hc1 = hcr[1];
    const float4* bgr = (const float4*)(bgl + sl * 8);
    float4 bg0 = bgr[0], bg1 = bgr[1];
    float t8[8];
    t8[0] = hc0.x + acc[0] * r + bg0.x;
    t8[1] = hc0.y + acc[1] * r + bg0.y;
    t8[2] = hc0.z + acc[2] * r + bg0.z;
    t8[3] = hc0.w + acc[3] * r + bg0.w;
    t8[4] = hc1.x + acc[4] * r + bg1.x;
    t8[5] = hc1.y + acc[5] * r + bg1.y;
    t8[6] = hc1.z + acc[6] * r + bg1.z;
    t8[7] = hc1.w + acc[7] * r + bg1.w;
    float sm = 0.f, sq = 0.f;
#pragma unroll
    for (int q = 0; q < 8; q++) { sm += t8[q]; sq += t8[q] * t8[q]; }
    sm = warp_sum(sm);  // both halves duplicate -> 2x channel sum
    sq = warp_sum(sq);
    float mu = sm * (1.f / 256.f);
    float var = sq * (1.f / 256.f) - mu * mu;
    float rs = rsqrtf(var + 1e-5f);
    if (half == 0) {
        const float4* gr = (const float4*)(lng + sl * 8);
        const float4* br = (const float4*)(lnb + sl * 8);
        float4 g0 = gr[0], g1 = gr[1];
        float4 b0 = br[0], b1 = br[1];
        float4 o0, o1;
        o0.x = (t8[0] - mu) * rs * g0.x + b0.x;
        o0.y = (t8[1] - mu) * rs * g0.y + b0.y;
        o0.z = (t8[2] - mu) * rs * g0.z + b0.z;
        o0.w = (t8[3] - mu) * rs * g0.w + b0.w;
        o1.x = (t8[4] - mu) * rs * g1.x + b1.x;
        o1.y = (t8[5] - mu) * rs * g1.y + b1.y;
        o1.z = (t8[6] - mu) * rs * g1.z + b1.z;
        o1.w = (t8[7] - mu) * rs * g1.w + b1.w;
        float4* outp = (float4*)(hnext + (size_t)gw * HID + sl * 8);
        outp[0] = o0;
        outp[1] = o1;
    }
}

// ---------------- launch ----------------
extern "C" void kernel_launch(void* const* d_in, const int* in_sizes, int n_in,
                              void* d_out, int out_size) {
    const float* x = (const float*)d_in[0];
    const int* ei = (const int*)d_in[1];
    const float* ea = (const float*)d_in[2];
    const float* W_in = (const float*)d_in[3];
    const float* b_in = (const float*)d_in[4];
    const float* ln_in_g = (const float*)d_in[5];
    const float* ln_in_b = (const float*)d_in[6];
    const float* Wg = (const float*)d_in[7];
    const float* att_src = (const float*)d_in[8];
    const float* att_dst = (const float*)d_in[9];
    const float* We = (const float*)d_in[10];
    const float* att_edge = (const float*)d_in[11];
    const float* bg = (const float*)d_in[12];
    const float* ln_g = (const float*)d_in[13];
    const float* ln_b = (const float*)d_in[14];
    const float* W1 = (const float*)d_in[15];
    const float* b1 = (const float*)d_in[16];
    const float* W2 = (const float*)d_in[17];
    const float* b2 = (const float*)d_in[18];

    int Nn = in_sizes[0] / 16;   // 100000
    int Ee = in_sizes[2] / 4;    // 1600000

    float *hA, *hB, *weh, *ad;
    __half *hp16, *as16;
    __nv_bfloat16 *Bh, *Bl;
    cudaGetSymbolAddress((void**)&hA, g_hA);
    cudaGetSymbolAddress((void**)&hB, g_hB);
    cudaGetSymbolAddress((void**)&hp16, g_hp16);
    cudaGetSymbolAddress((void**)&weh, g_weh);
    cudaGetSymbolAddress((void**)&as16, g_as16);
    cudaGetSymbolAddress((void**)&ad, g_ad);
    cudaGetSymbolAddress((void**)&Bh, g_Bh);
    cudaGetSymbolAddress((void**)&Bl, g_Bl);

    cudaFuncSetAttribute(k_mma<0>, cudaFuncAttributeMaxDynamicSharedMemorySize, SM_TOT);
    cudaFuncSetAttribute(k_mma<1>, cudaFuncAttributeMaxDynamicSharedMemorySize, SM_TOT);

    int nwb = (Nn + 7) / 8;
    int mb = (Nn + 63) / 64;

    // ---- independent prep first, layer-0 GEMM at launch position 4 (ncu target) ----
    k_prep_bsplit<<<NLAYERS + 1, 128>>>(Wg, W1);                               // 1
    k_input<<<nwb, 256>>>(x, W_in, b_in, ln_in_g, ln_in_b, hA, Nn);            // 2
    k_prep_weh<<<NLAYERS, 32>>>(We, att_edge);                                 // 3
    k_mma<0><<<mb, 256, SM_TOT>>>(hA, Bh, Bl, att_src, att_dst,                // 4 <- ncu target
                                  hp16, as16, ad, nullptr, nullptr, nullptr, Nn);

    // ---- CSR preprocessing ----
    k_zero<<<(Nn + 255) / 256, 256>>>(Nn);
    k_hist<<<(Ee + 255) / 256, 256>>>(ei, Ee);
    int nb = (Nn + 1023) / 1024;
    k_scan1<<<nb, 1024>>>(Nn);
    k_scan2<<<1, 32>>>(nb);
    k_scan3<<<nb, 1024>>>(Nn);
    k_scatter<<<(Ee + 255) / 256, 256>>>(ei, Ee);
    k_sortfix<<<(Nn + 255) / 256, 256>>>(ei, (const float4*)ea, Nn);

    // ---- degree-sorted node schedule (balance edge-kernel warps) ----
    k_dhist<<<(Nn + 255) / 256, 256>>>(Nn);
    k_dscan<<<1, 32>>>();
    k_dscatter<<<(Nn + 255) / 256, 256>>>(Nn);

    // ---- GAT layers (layer 0 GEMM already done) ----
    float* hcur = hA;
    float* hnxt = hB;
    for (int l = 0; l < NLAYERS; l++) {
        if (l > 0) {
            k_mma<0><<<mb, 256, SM_TOT>>>(hcur, Bh + (size_t)l * HID * HID,
                                          Bl + (size_t)l * HID * HID,
                                          att_src + l * HID, att_dst + l * HID,
                                          hp16, as16, ad, nullptr, nullptr, nullptr, Nn);
        }
        k_gat_edge<<<nwb, 256>>>(hcur, weh + l * 32, bg + l * HID,
                                 ln_g + l * HID, ln_b + l * HID, hnxt, Nn);
        float* t = hcur; hcur = hnxt; hnxt = t;
    }

    // ---- output head (fully fused into k_mma<1>) ----
    k_mma<1><<<mb, 256, SM_TOT>>>(hcur, Bh + (size_t)NLAYERS * HID * HID,
                                  Bl + (size_t)NLAYERS * HID * HID,
                                  b1, b1, nullptr, nullptr, nullptr,
                                  W2, b2, (float*)d_out, Nn);
}

// round 14
// speedup vs baseline: 1.0568x; 1.0568x over previous
#include <cuda_runtime.h>
#include <cuda_bf16.h>
#include <cuda_fp16.h>
#include <cstdint>

#define NMAX 100000
#define EMAX 1600000
#define HID 128
#define HEADS 8
#define NLAYERS 6
#define LOG2E 1.44269504f

// ---------------- scratch (device globals; no allocation allowed) ----------------
__device__ __align__(16) float g_hA[(size_t)NMAX * HID];
__device__ __align__(16) float g_hB[(size_t)NMAX * HID];
__device__ __align__(16) __half g_hp16[(size_t)NMAX * HID];    // fp16 messages
__device__ __align__(16) __half g_as16[(size_t)NMAX * HEADS];  // fp16 alpha_src (x log2e)
__device__ __align__(16) float g_ad[(size_t)NMAX * HEADS];     // fp32 alpha_dst (x log2e)
__device__ int g_off[NMAX + 1];
__device__ int g_deg[NMAX];
__device__ int g_cnt[NMAX];
__device__ int g_bsum[256];
__device__ int g_eid[EMAX];
__device__ int g_srcS[EMAX];
__device__ __align__(8) uint2 g_eaS2[EMAX];  // half4 edge attrs, dst-sorted
__device__ float g_weh[NLAYERS * 4 * HEADS]; // x log2e
// pre-split transposed weights: [7][n=128][k=128] bf16 (6 GAT layers + W1)
__device__ __align__(16) __nv_bfloat16 g_Bh[7 * 128 * 128];
__device__ __align__(16) __nv_bfloat16 g_Bl[7 * 128 * 128];

// ---------------- utils ----------------
__device__ __forceinline__ float warp_sum(float v) {
#pragma unroll
    for (int o = 16; o; o >>= 1) v += __shfl_xor_sync(0xffffffffu, v, o);
    return v;
}

__device__ __forceinline__ float ex2(float x) {
    float y;
    asm("ex2.approx.ftz.f32 %0, %1;" : "=f"(y) : "f"(x));
    return y;
}

__device__ __forceinline__ uint32_t smem_u32(const void* p) {
    uint32_t a;
    asm("{ .reg .u64 t; cvta.to.shared.u64 t, %1; cvt.u32.u64 %0, t; }" : "=r"(a) : "l"(p));
    return a;
}

__device__ __forceinline__ void mma16816(float* d, uint32_t a0, uint32_t a1, uint32_t a2,
                                         uint32_t a3, uint32_t b0, uint32_t b1) {
    asm volatile(
        "mma.sync.aligned.m16n8k16.row.col.f32.bf16.bf16.f32 "
        "{%0,%1,%2,%3}, {%4,%5,%6,%7}, {%8,%9}, {%0,%1,%2,%3};"
        : "+f"(d[0]), "+f"(d[1]), "+f"(d[2]), "+f"(d[3])
        : "r"(a0), "r"(a1), "r"(a2), "r"(a3), "r"(b0), "r"(b1));
}

__device__ __forceinline__ void ldsm_x4(uint32_t& r0, uint32_t& r1, uint32_t& r2, uint32_t& r3,
                                        uint32_t addr) {
    asm volatile("ldmatrix.sync.aligned.m8n8.x4.shared.b16 {%0,%1,%2,%3}, [%4];"
                 : "=r"(r0), "=r"(r1), "=r"(r2), "=r"(r3) : "r"(addr));
}

// ---------------- preprocessing ----------------
__global__ void k_zero(int n) {
    int i = blockIdx.x * blockDim.x + threadIdx.x;
    if (i < n) { g_deg[i] = 0; g_cnt[i] = 0; }
}

__global__ void k_hist(const int* __restrict__ ei, int Ee) {
    int e = blockIdx.x * blockDim.x + threadIdx.x;
    if (e < Ee) atomicAdd(&g_deg[ei[Ee + e]], 1);
}

__global__ void k_scan1(int n) {
    __shared__ int ws[32];
    int i = blockIdx.x * 1024 + threadIdx.x;
    int lane = threadIdx.x & 31, wid = threadIdx.x >> 5;
    int v = (i < n) ? g_deg[i] : 0;
    int x = v;
#pragma unroll
    for (int o = 1; o < 32; o <<= 1) {
        int y = __shfl_up_sync(0xffffffffu, x, o);
        if (lane >= o) x += y;
    }
    if (lane == 31) ws[wid] = x;
    __syncthreads();
    if (wid == 0) {
        int y = ws[lane];
#pragma unroll
        for (int o = 1; o < 32; o <<= 1) {
            int z = __shfl_up_sync(0xffffffffu, y, o);
            if (lane >= o) y += z;
        }
        ws[lane] = y;
    }
    __syncthreads();
    int inc = x + (wid > 0 ? ws[wid - 1] : 0);
    if (i < n) g_off[i] = inc - v;
    if (threadIdx.x == 1023) g_bsum[blockIdx.x] = inc;
}

__global__ void k_scan2(int nb) {
    int lane = threadIdx.x;  // 32 threads
    int run = 0;
    for (int base = 0; base < nb; base += 32) {
        int idx = base + lane;
        int v = (idx < nb) ? g_bsum[idx] : 0;
        int x = v;
#pragma unroll
        for (int o = 1; o < 32; o <<= 1) {
            int y = __shfl_up_sync(0xffffffffu, x, o);
            if (lane >= o) x += y;
        }
        if (idx < nb) g_bsum[idx] = x - v + run;
        run += __shfl_sync(0xffffffffu, x, 31);
    }
    if (lane == 0) g_bsum[nb] = run;
}

__global__ void k_scan3(int n) {
    int i = blockIdx.x * 1024 + threadIdx.x;
    if (i < n) g_off[i] += g_bsum[blockIdx.x];
    if (i == 0) g_off[n] = g_bsum[gridDim.x];
}

__global__ void k_scatter(const int* __restrict__ ei, int Ee) {
    int e = blockIdx.x * blockDim.x + threadIdx.x;
    if (e >= Ee) return;
    int d = ei[Ee + e];
    int p = g_off[d] + atomicAdd(&g_cnt[d], 1);
    g_eid[p] = e;
}

__device__ __forceinline__ uint2 pack_half4(float4 v) {
    __half2 p0 = __floats2half2_rn(v.x, v.y);
    __half2 p1 = __floats2half2_rn(v.z, v.w);
    uint2 u;
    u.x = *reinterpret_cast<uint32_t*>(&p0);
    u.y = *reinterpret_cast<uint32_t*>(&p1);
    return u;
}

__global__ void k_sortfix(const int* __restrict__ ei, const float4* __restrict__ ea, int Nn) {
    int n = blockIdx.x * blockDim.x + threadIdx.x;
    if (n >= Nn) return;
    int st = g_off[n], en = g_off[n + 1];
    int d = en - st;
    if (d <= 0) return;
    if (d <= 192) {
        int a[192];
        for (int i = 0; i < d; i++) a[i] = g_eid[st + i];
        for (int i = 1; i < d; i++) {
            int key = a[i]; int j = i - 1;
            while (j >= 0 && a[j] > key) { a[j + 1] = a[j]; j--; }
            a[j + 1] = key;
        }
        for (int i = 0; i < d; i++) {
            int eid = a[i];
            g_srcS[st + i] = ei[eid];
            g_eaS2[st + i] = pack_half4(ea[eid]);
        }
    } else {
        for (int i = 0; i < d - 1; i++) {
            int mn = i;
            for (int j = i + 1; j < d; j++)
                if (g_eid[st + j] < g_eid[st + mn]) mn = j;
            int t = g_eid[st + i]; g_eid[st + i] = g_eid[st + mn]; g_eid[st + mn] = t;
        }
        for (int i = 0; i < d; i++) {
            int eid = g_eid[st + i];
            g_srcS[st + i] = ei[eid];
            g_eaS2[st + i] = pack_half4(ea[eid]);
        }
    }
}

// edge attention weights folded per layer (x log2e)
__global__ void k_prep_weh(const float* __restrict__ We, const float* __restrict__ aev) {
    int l = blockIdx.x;
    int t = threadIdx.x;  // 32
    int d = t >> 3, h = t & 7;
    float s = 0.f;
#pragma unroll
    for (int c = 0; c < 16; c++)
        s += We[l * 4 * HID + d * HID + h * 16 + c] * aev[l * HID + h * 16 + c];
    g_weh[l * 32 + d * 8 + h] = s * LOG2E;
}

// transpose + bf16-split weights
__global__ void k_prep_bsplit(const float* __restrict__ Wg, const float* __restrict__ W1) {
    int l = blockIdx.x;
    const float* W = (l < NLAYERS) ? (Wg + (size_t)l * HID * HID) : W1;
    int n = threadIdx.x;
    __nv_bfloat16* bh = g_Bh + (size_t)l * HID * HID;
    __nv_bfloat16* bl = g_Bl + (size_t)l * HID * HID;
    for (int k = 0; k < HID; k++) {
        float v = W[k * HID + n];
        __nv_bfloat16 hb = __float2bfloat16(v);
        float r = v - __bfloat162float(hb);
        bh[n * HID + k] = hb;
        bl[n * HID + k] = __float2bfloat16(r);
    }
}

// ---------------- input projection: h0 = LN(relu(x @ W_in + b_in)) ----------------
__global__ void k_input(const float* __restrict__ x, const float* __restrict__ Win,
                        const float* __restrict__ bin, const float* __restrict__ g,
                        const float* __restrict__ b, float* __restrict__ h0, int Nn) {
    __shared__ float Ws[16 * HID];
    for (int i = threadIdx.x; i < 16 * HID; i += blockDim.x) Ws[i] = Win[i];
    __syncthreads();
    int gw = (blockIdx.x * blockDim.x + threadIdx.x) >> 5;
    if (gw >= Nn) return;
    int lane = threadIdx.x & 31;
    float4 bv = ((const float4*)bin)[lane];
    float acc0 = bv.x, acc1 = bv.y, acc2 = bv.z, acc3 = bv.w;
#pragma unroll
    for (int k = 0; k < 16; k++) {
        float xv = __ldg(x + (size_t)gw * 16 + k);
        acc0 += xv * Ws[k * HID + lane * 4 + 0];
        acc1 += xv * Ws[k * HID + lane * 4 + 1];
        acc2 += xv * Ws[k * HID + lane * 4 + 2];
        acc3 += xv * Ws[k * HID + lane * 4 + 3];
    }
    float t0 = fmaxf(acc0, 0.f), t1 = fmaxf(acc1, 0.f), t2 = fmaxf(acc2, 0.f), t3 = fmaxf(acc3, 0.f);
    float sm = warp_sum(t0 + t1 + t2 + t3);
    float sq = warp_sum(t0 * t0 + t1 * t1 + t2 * t2 + t3 * t3);
    float mu = sm * (1.f / 128.f);
    float var = sq * (1.f / 128.f) - mu * mu;
    float rs = rsqrtf(var + 1e-5f);
    float4 gv = ((const float4*)g)[lane];
    float4 bbv = ((const float4*)b)[lane];
    float4 o;
    o.x = (t0 - mu) * rs * gv.x + bbv.x;
    o.y = (t1 - mu) * rs * gv.y + bbv.y;
    o.z = (t2 - mu) * rs * gv.z + bbv.z;
    o.w = (t3 - mu) * rs * gv.w + bbv.w;
    ((float4*)(h0 + (size_t)gw * HID))[lane] = o;
}

// ---------------- HMMA GEMM: C[M,128] = A[M,128] @ W[128,128] via bf16x3 split ----
// M-tile 64 (2 CTAs/SM), warp layout 2(M) x 4(N). Fragments via ldmatrix.x4.
// MODE 0: C -> fp16 hp, fused fp16 alpha_src + fp32 alpha_dst epilogue (x log2e)
// MODE 1: fused output head: out = relu(relu(C + b1) @ W2 + b2), OUT_DIM=3
#define RS 272
#define OFF_AHI 0
#define OFF_ALO 17408
#define OFF_BHI 34816
#define OFF_BLO 69632
#define OFF_ATT 104448
#define SM_TOT  105472

template <int MODE>
__global__ void __launch_bounds__(256, 2) k_mma(
    const float* __restrict__ A, const __nv_bfloat16* __restrict__ BhG,
    const __nv_bfloat16* __restrict__ BlG, const float* __restrict__ v1,
    const float* __restrict__ v2, __half* __restrict__ Ch,
    __half* __restrict__ oAS, float* __restrict__ oAD,
    const float* __restrict__ W2g, const float* __restrict__ b2g,
    float* __restrict__ outg, int M) {
    extern __shared__ char smem[];
    char* Ahi = smem + OFF_AHI;
    char* Alo = smem + OFF_ALO;
    char* Bhi = smem + OFF_BHI;
    char* Blo = smem + OFF_BLO;
    float* att = (float*)(smem + OFF_ATT);
    float* Cs = (float*)smem;  // reused after compute (row stride 132 floats)
    const int tid = threadIdx.x;
    const int m0 = blockIdx.x * 64;

    if (MODE == 0) {
        if (tid < 128) att[tid] = v1[tid] * LOG2E;
        else att[tid] = v2[tid - 128] * LOG2E;
    } else {
        if (tid < 128) att[tid] = v1[tid];
    }

    // ---- fill A (64 rows): fp32 -> bf16 hi/lo ----
#pragma unroll
    for (int it = 0; it < 4; it++) {
        int q = tid + it * 256;
        int r = q >> 4, w = q & 15;
        int m = m0 + r;
        float f[8];
        if (m < M) {
            const float* ar = A + (size_t)m * HID + w * 8;
            float4 x0 = *(const float4*)ar;
            float4 x1 = *(const float4*)(ar + 4);
            f[0] = x0.x; f[1] = x0.y; f[2] = x0.z; f[3] = x0.w;
            f[4] = x1.x; f[5] = x1.y; f[6] = x1.z; f[7] = x1.w;
        } else {
#pragma unroll
            for (int i = 0; i < 8; i++) f[i] = 0.f;
        }
        uint32_t hu[8], lu[8];
#pragma unroll
        for (int i = 0; i < 8; i++) {
            __nv_bfloat16 hb = __float2bfloat16(f[i]);
            float rr = f[i] - __bfloat162float(hb);
            hu[i] = (uint32_t)__bfloat16_as_ushort(hb);
            lu[i] = (uint32_t)__bfloat16_as_ushort(__float2bfloat16(rr));
        }
        uint4 ph, pl;
        ph.x = hu[0] | (hu[1] << 16); ph.y = hu[2] | (hu[3] << 16);
        ph.z = hu[4] | (hu[5] << 16); ph.w = hu[6] | (hu[7] << 16);
        pl.x = lu[0] | (lu[1] << 16); pl.y = lu[2] | (lu[3] << 16);
        pl.z = lu[4] | (lu[5] << 16); pl.w = lu[6] | (lu[7] << 16);
        *(uint4*)(Ahi + r * RS + w * 16) = ph;
        *(uint4*)(Alo + r * RS + w * 16) = pl;
    }
    // ---- fill B (pre-split bf16 [n][k], 256B rows, 128 rows) ----
#pragma unroll
    for (int it = 0; it < 8; it++) {
        int q = tid + it * 256;
        int r = q >> 4, w = q & 15;
        *(uint4*)(Bhi + r * RS + w * 16) = *(const uint4*)((const char*)BhG + r * 256 + w * 16);
        *(uint4*)(Blo + r * RS + w * 16) = *(const uint4*)((const char*)BlG + r * 256 + w * 16);
    }
    __syncthreads();

    const int wid = tid >> 5, lane = tid & 31;
    const int cq = lane & 3, gq = lane >> 2;
    const int mb = (wid & 1) * 32;
    const int nb = (wid >> 1) * 32;

    float acc[2][4][4];
#pragma unroll
    for (int a = 0; a < 2; a++)
#pragma unroll
        for (int j = 0; j < 4; j++)
#pragma unroll
            for (int i = 0; i < 4; i++) acc[a][j][i] = 0.f;

    const uint32_t sbase = smem_u32(smem);
    const int l7 = lane & 7;
    const uint32_t aAddr = sbase + OFF_AHI +
        (uint32_t)(mb + l7 + ((lane >> 3) & 1) * 8) * RS + ((lane >> 4) & 1) * 16;
    const uint32_t bAddr = sbase + OFF_BHI +
        (uint32_t)(nb + ((lane >> 4) & 1) * 8 + l7) * RS + ((lane >> 3) & 1) * 16;
    const uint32_t ALO_D = OFF_ALO - OFF_AHI;
    const uint32_t BLO_D = OFF_BLO - OFF_BHI;

#pragma unroll
    for (int kc = 0; kc < 8; kc++) {
        const uint32_t kby = kc * 32;
        uint32_t ah[2][4], al[2][4], bh[4][2], bl[4][2];
        ldsm_x4(ah[0][0], ah[0][1], ah[0][2], ah[0][3], aAddr + kby);
        ldsm_x4(ah[1][0], ah[1][1], ah[1][2], ah[1][3], aAddr + 16 * RS + kby);
        ldsm_x4(al[0][0], al[0][1], al[0][2], al[0][3], aAddr + ALO_D + kby);
        ldsm_x4(al[1][0], al[1][1], al[1][2], al[1][3], aAddr + ALO_D + 16 * RS + kby);
        ldsm_x4(bh[0][0], bh[0][1], bh[1][0], bh[1][1], bAddr + kby);
        ldsm_x4(bh[2][0], bh[2][1], bh[3][0], bh[3][1], bAddr + 16 * RS + kby);
        ldsm_x4(bl[0][0], bl[0][1], bl[1][0], bl[1][1], bAddr + BLO_D + kby);
        ldsm_x4(bl[2][0], bl[2][1], bl[3][0], bl[3][1], bAddr + BLO_D + 16 * RS + kby);
#pragma unroll
        for (int j = 0; j < 4; j++) {
#pragma unroll
            for (int mt = 0; mt < 2; mt++) {
                mma16816(acc[mt][j], ah[mt][0], ah[mt][1], ah[mt][2], ah[mt][3],
                         bh[j][0], bh[j][1]);
                mma16816(acc[mt][j], al[mt][0], al[mt][1], al[mt][2], al[mt][3],
                         bh[j][0], bh[j][1]);
                mma16816(acc[mt][j], ah[mt][0], ah[mt][1], ah[mt][2], ah[mt][3],
                         bl[j][0], bl[j][1]);
            }
        }
    }

    // ---- fused alpha epilogue (MODE 0): alpha_src -> fp16, alpha_dst -> fp32 ----
    if (MODE == 0) {
        float sAS[2][2][2], sAD[2][2][2];
#pragma unroll
        for (int a = 0; a < 2; a++)
#pragma unroll
            for (int hf = 0; hf < 2; hf++)
#pragma unroll
                for (int h = 0; h < 2; h++) { sAS[a][hf][h] = 0.f; sAD[a][hf][h] = 0.f; }
#pragma unroll
        for (int mt = 0; mt < 2; mt++)
#pragma unroll
            for (int j = 0; j < 4; j++) {
                int hl = j >> 1;
                int col = nb + j * 8 + 2 * cq;
                float w0 = att[col], w1 = att[col + 1];
                float u0 = att[128 + col], u1 = att[128 + col + 1];
                sAS[mt][0][hl] += acc[mt][j][0] * w0 + acc[mt][j][1] * w1;
                sAS[mt][1][hl] += acc[mt][j][2] * w0 + acc[mt][j][3] * w1;
                sAD[mt][0][hl] += acc[mt][j][0] * u0 + acc[mt][j][1] * u1;
                sAD[mt][1][hl] += acc[mt][j][2] * u0 + acc[mt][j][3] * u1;
            }
#pragma unroll
        for (int mt = 0; mt < 2; mt++)
#pragma unroll
            for (int hf = 0; hf < 2; hf++)
#pragma unroll
                for (int h = 0; h < 2; h++) {
                    float v = sAS[mt][hf][h];
                    v += __shfl_xor_sync(0xffffffffu, v, 1);
                    v += __shfl_xor_sync(0xffffffffu, v, 2);
                    sAS[mt][hf][h] = v;
                    float u = sAD[mt][hf][h];
                    u += __shfl_xor_sync(0xffffffffu, u, 1);
                    u += __shfl_xor_sync(0xffffffffu, u, 2);
                    sAD[mt][hf][h] = u;
                }
        if (cq == 0) {
#pragma unroll
            for (int mt = 0; mt < 2; mt++)
#pragma unroll
                for (int hf = 0; hf < 2; hf++) {
                    int r = m0 + mb + mt * 16 + hf * 8 + gq;
                    if (r < M) {
                        __half2 p = __floats2half2_rn(sAS[mt][hf][0], sAS[mt][hf][1]);
                        *(uint32_t*)(oAS + (size_t)r * 8 + (nb >> 4)) =
                            *reinterpret_cast<uint32_t*>(&p);
                        *(float2*)(oAD + (size_t)r * 8 + (nb >> 4)) =
                            make_float2(sAD[mt][hf][0], sAD[mt][hf][1]);
                    }
                }
        }
    }

    // ---- stage C in SMEM ----
    __syncthreads();
#pragma unroll
    for (int mt = 0; mt < 2; mt++)
#pragma unroll
        for (int j = 0; j < 4; j++) {
            int row = mb + mt * 16 + gq;
            int col = nb + j * 8 + 2 * cq;
            *(float2*)(Cs + row * 132 + col) = make_float2(acc[mt][j][0], acc[mt][j][1]);
            *(float2*)(Cs + (row + 8) * 132 + col) = make_float2(acc[mt][j][2], acc[mt][j][3]);
        }
    __syncthreads();

    if (MODE == 0) {
        // write hp as fp16, coalesced
#pragma unroll
        for (int it = 0; it < 8; it++) {
            int q = tid + it * 256;
            int r = q >> 5, w = q & 31;
            int m = m0 + r;
            if (m < M) {
                float4 v = *(float4*)(Cs + r * 132 + w * 4);
                __half2 p0 = __floats2half2_rn(v.x, v.y);
                __half2 p1 = __floats2half2_rn(v.z, v.w);
                uint2 u;
                u.x = *reinterpret_cast<uint32_t*>(&p0);
                u.y = *reinterpret_cast<uint32_t*>(&p1);
                *(uint2*)(Ch + (size_t)m * HID + w * 4) = u;
            }
        }
    } else {
        // fused output head: out[m] = relu( relu(C[m]+b1) @ W2 + b2 ), OUT_DIM=3
        int r = tid >> 2;       // row 0..63
        int qq = tid & 3;       // channel quarter
        int m = m0 + r;
        float p0 = 0.f, p1 = 0.f, p2 = 0.f;
        const float* cr = Cs + r * 132 + qq * 32;
        const float* ar = att + qq * 32;
        const float* w2 = W2g + qq * 32 * 3;
#pragma unroll
        for (int i = 0; i < 32; i++) {
            float v = fmaxf(cr[i] + ar[i], 0.f);
            p0 = fmaf(v, __ldg(&w2[i * 3 + 0]), p0);
            p1 = fmaf(v, __ldg(&w2[i * 3 + 1]), p1);
            p2 = fmaf(v, __ldg(&w2[i * 3 + 2]), p2);
        }
        p0 += __shfl_xor_sync(0xffffffffu, p0, 1);
        p0 += __shfl_xor_sync(0xffffffffu, p0, 2);
        p1 += __shfl_xor_sync(0xffffffffu, p1, 1);
        p1 += __shfl_xor_sync(0xffffffffu, p1, 2);
        p2 += __shfl_xor_sync(0xffffffffu, p2, 1);
        p2 += __shfl_xor_sync(0xffffffffu, p2, 2);
        if (qq == 0 && m < M) {
            outg[(size_t)m * 3 + 0] = fmaxf(p0 + __ldg(&b2g[0]), 0.f);
            outg[(size_t)m * 3 + 1] = fmaxf(p1 + __ldg(&b2g[1]), 0.f);
            outg[(size_t)m * 3 + 2] = fmaxf(p2 + __ldg(&b2g[2]), 0.f);
        }
    }
}

// ---------------- fused attention + aggregation + residual + LN (R7 champion) ----
// Half-warp per edge; each lane covers 8 channels; 1-ahead (src,ea) prefetch.
// 128-thread blocks: finer retirement granularity vs degree stragglers.
__global__ void k_gat_edge(const float* __restrict__ hcur, const float* __restrict__ weh_l,
                           const float* __restrict__ bgl, const float* __restrict__ lng,
                           const float* __restrict__ lnb, float* __restrict__ hnext, int Nn) {
    int gw = (blockIdx.x * blockDim.x + threadIdx.x) >> 5;
    if (gw >= Nn) return;
    int lane = threadIdx.x & 31;
    int half = lane >> 4;
    int sl = lane & 15;      // channel group: 8*sl .. 8*sl+7
    int hh = sl >> 1;        // head
    float adv = __ldg(&g_ad[(size_t)gw * 8 + hh]);
    float w0 = __ldg(&weh_l[0 * 8 + hh]);
    float w1 = __ldg(&weh_l[1 * 8 + hh]);
    float w2 = __ldg(&weh_l[2 * 8 + hh]);
    float w3 = __ldg(&weh_l[3 * 8 + hh]);
    int s0 = g_off[gw], s1 = g_off[gw + 1];
    int d = s1 - s0;

    float acc[8];
#pragma unroll
    for (int q = 0; q < 8; q++) acc[q] = 0.f;
    float den = 0.f;

    int i = half;
    int sP = 0; uint2 eaP = make_uint2(0, 0);
    if (i < d) { sP = __ldg(&g_srcS[s0 + i]); eaP = g_eaS2[s0 + i]; }
    for (; i < d; i += 2) {
        int s = sP; uint2 eau = eaP;
        if (i + 2 < d) { sP = __ldg(&g_srcS[s0 + i + 2]); eaP = g_eaS2[s0 + i + 2]; }
        float asv = __half2float(g_as16[(size_t)s * 8 + hh]);
        float2 f01 = __half22float2(*reinterpret_cast<__half2*>(&eau.x));
        float2 f23 = __half22float2(*reinterpret_cast<__half2*>(&eau.y));
        float al = asv + adv + f01.x * w0 + f01.y * w1 + f23.x * w2 + f23.y * w3;
        al = fmaxf(al, 0.2f * al);
        float a = ex2(al);
        den += a;
        uint4 hv = *(const uint4*)(g_hp16 + (size_t)s * HID + sl * 8);
        __half2* hp2 = reinterpret_cast<__half2*>(&hv);
#pragma unroll
        for (int q = 0; q < 4; q++) {
            float2 f = __half22float2(hp2[q]);
            acc[2 * q] = fmaf(a, f.x, acc[2 * q]);
            acc[2 * q + 1] = fmaf(a, f.y, acc[2 * q + 1]);
        }
    }

    // merge even/odd halves (fixed order)
#pragma unroll
    for (int q = 0; q < 8; q++) acc[q] += __shfl_xor_sync(0xffffffffu, acc[q], 16);
    den += __shfl_xor_sync(0xffffffffu, den, 16);

    float r = 1.f / (den + 1e-16f);
    const float4* hcr = (const float4*)(hcur + (size_t)gw * HID + sl * 8);
    float4 hc0 = hcr[0], hc1 = hcr[1];
    const float4* bgr = (const float4*)(bgl + sl * 8);
    float4 bg0 = bgr[0], bg1 = bgr[1];
    float t8[8];
    t8[0] = hc0.x + acc[0] * r + bg0.x;
    t8[1] = hc0.y + acc[1] * r + bg0.y;
    t8[2] = hc0.z + acc[2] * r + bg0.z;
    t8[3] = hc0.w + acc[3] * r + bg0.w;
    t8[4] = hc1.x + acc[4] * r + bg1.x;
    t8[5] = hc1.y + acc[5] * r + bg1.y;
    t8[6] = hc1.z + acc[6] * r + bg1.z;
    t8[7] = hc1.w + acc[7] * r + bg1.w;
    float sm = 0.f, sq = 0.f;
#pragma unroll
    for (int q = 0; q < 8; q++) { sm += t8[q]; sq += t8[q] * t8[q]; }
    sm = warp_sum(sm);  // both halves duplicate -> 2x channel sum
    sq = warp_sum(sq);
    float mu = sm * (1.f / 256.f);
    float var = sq * (1.f / 256.f) - mu * mu;
    float rs = rsqrtf(var + 1e-5f);
    if (half == 0) {
        const float4* gr = (const float4*)(lng + sl * 8);
        const float4* br = (const float4*)(lnb + sl * 8);
        float4 g0 = gr[0], g1 = gr[1];
        float4 b0 = br[0], b1 = br[1];
        float4 o0, o1;
        o0.x = (t8[0] - mu) * rs * g0.x + b0.x;
        o0.y = (t8[1] - mu) * rs * g0.y + b0.y;
        o0.z = (t8[2] - mu) * rs * g0.z + b0.z;
        o0.w = (t8[3] - mu) * rs * g0.w + b0.w;
        o1.x = (t8[4] - mu) * rs * g1.x + b1.x;
        o1.y = (t8[5] - mu) * rs * g1.y + b1.y;
        o1.z = (t8[6] - mu) * rs * g1.z + b1.z;
        o1.w = (t8[7] - mu) * rs * g1.w + b1.w;
        float4* outp = (float4*)(hnext + (size_t)gw * HID + sl * 8);
        outp[0] = o0;
        outp[1] = o1;
    }
}

// ---------------- launch ----------------
extern "C" void kernel_launch(void* const* d_in, const int* in_sizes, int n_in,
                              void* d_out, int out_size) {
    const float* x = (const float*)d_in[0];
    const int* ei = (const int*)d_in[1];
    const float* ea = (const float*)d_in[2];
    const float* W_in = (const float*)d_in[3];
    const float* b_in = (const float*)d_in[4];
    const float* ln_in_g = (const float*)d_in[5];
    const float* ln_in_b = (const float*)d_in[6];
    const float* Wg = (const float*)d_in[7];
    const float* att_src = (const float*)d_in[8];
    const float* att_dst = (const float*)d_in[9];
    const float* We = (const float*)d_in[10];
    const float* att_edge = (const float*)d_in[11];
    const float* bg = (const float*)d_in[12];
    const float* ln_g = (const float*)d_in[13];
    const float* ln_b = (const float*)d_in[14];
    const float* W1 = (const float*)d_in[15];
    const float* b1 = (const float*)d_in[16];
    const float* W2 = (const float*)d_in[17];
    const float* b2 = (const float*)d_in[18];

    int Nn = in_sizes[0] / 16;   // 100000
    int Ee = in_sizes[2] / 4;    // 1600000

    float *hA, *hB, *weh, *ad;
    __half *hp16, *as16;
    __nv_bfloat16 *Bh, *Bl;
    cudaGetSymbolAddress((void**)&hA, g_hA);
    cudaGetSymbolAddress((void**)&hB, g_hB);
    cudaGetSymbolAddress((void**)&hp16, g_hp16);
    cudaGetSymbolAddress((void**)&weh, g_weh);
    cudaGetSymbolAddress((void**)&as16, g_as16);
    cudaGetSymbolAddress((void**)&ad, g_ad);
    cudaGetSymbolAddress((void**)&Bh, g_Bh);
    cudaGetSymbolAddress((void**)&Bl, g_Bl);

    cudaFuncSetAttribute(k_mma<0>, cudaFuncAttributeMaxDynamicSharedMemorySize, SM_TOT);
    cudaFuncSetAttribute(k_mma<1>, cudaFuncAttributeMaxDynamicSharedMemorySize, SM_TOT);

    int nwb = (Nn + 7) / 8;       // 256-thread blocks (input proj)
    int neb = (Nn + 3) / 4;       // 128-thread blocks (edge kernel)
    int mb = (Nn + 63) / 64;

    // ---- independent prep first, layer-0 GEMM at launch position 4 (ncu target) ----
    k_prep_bsplit<<<NLAYERS + 1, 128>>>(Wg, W1);                               // 1
    k_input<<<nwb, 256>>>(x, W_in, b_in, ln_in_g, ln_in_b, hA, Nn);            // 2
    k_prep_weh<<<NLAYERS, 32>>>(We, att_edge);                                 // 3
    k_mma<0><<<mb, 256, SM_TOT>>>(hA, Bh, Bl, att_src, att_dst,                // 4 <- ncu target
                                  hp16, as16, ad, nullptr, nullptr, nullptr, Nn);

    // ---- CSR preprocessing ----
    k_zero<<<(Nn + 255) / 256, 256>>>(Nn);
    k_hist<<<(Ee + 255) / 256, 256>>>(ei, Ee);
    int nb = (Nn + 1023) / 1024;
    k_scan1<<<nb, 1024>>>(Nn);
    k_scan2<<<1, 32>>>(nb);
    k_scan3<<<nb, 1024>>>(Nn);
    k_scatter<<<(Ee + 255) / 256, 256>>>(ei, Ee);
    k_sortfix<<<(Nn + 255) / 256, 256>>>(ei, (const float4*)ea, Nn);

    // ---- GAT layers (layer 0 GEMM already done) ----
    float* hcur = hA;
    float* hnxt = hB;
    for (int l = 0; l < NLAYERS; l++) {
        if (l > 0) {
            k_mma<0><<<mb, 256, SM_TOT>>>(hcur, Bh + (size_t)l * HID * HID,
                                          Bl + (size_t)l * HID * HID,
                                          att_src + l * HID, att_dst + l * HID,
                                          hp16, as16, ad, nullptr, nullptr, nullptr, Nn);
        }
        k_gat_edge<<<neb, 128>>>(hcur, weh + l * 32, bg + l * HID,
                                 ln_g + l * HID, ln_b + l * HID, hnxt, Nn);
        float* t = hcur; hcur = hnxt; hnxt = t;
    }

    // ---- output head (fully fused into k_mma<1>) ----
    k_mma<1><<<mb, 256, SM_TOT>>>(hcur, Bh + (size_t)NLAYERS * HID * HID,
                                  Bl + (size_t)NLAYERS * HID * HID,
                                  b1, b1, nullptr, nullptr, nullptr,
                                  W2, b2, (float*)d_out, Nn);
}

// round 15
// speedup vs baseline: 1.0643x; 1.0071x over previous
#include <cuda_runtime.h>
#include <cuda_bf16.h>
#include <cuda_fp16.h>
#include <cstdint>

#define NMAX 100000
#define EMAX 1600000
#define HID 128
#define HEADS 8
#define NLAYERS 6
#define LOG2E 1.44269504f

// ---------------- scratch (device globals; no allocation allowed) ----------------
__device__ __align__(16) float g_hA[(size_t)NMAX * HID];
__device__ __align__(16) float g_hB[(size_t)NMAX * HID];
__device__ __align__(16) __half g_hp16[(size_t)NMAX * HID];    // fp16 messages
__device__ __align__(16) __half g_as16[(size_t)NMAX * HEADS];  // fp16 alpha_src (x log2e)
__device__ __align__(16) float g_ad[(size_t)NMAX * HEADS];     // fp32 alpha_dst (x log2e)
__device__ int g_off[NMAX + 1];
__device__ int g_deg[NMAX];
__device__ int g_cnt[NMAX];
__device__ int g_bsum[256];
__device__ int g_eid[EMAX];
__device__ int g_srcS[EMAX];
__device__ __align__(8) uint2 g_eaS2[EMAX];  // half4 edge attrs, dst-sorted
__device__ float g_weh[NLAYERS * 4 * HEADS]; // x log2e
// pre-split transposed weights: [7][n=128][k=128] bf16 (6 GAT layers + W1)
__device__ __align__(16) __nv_bfloat16 g_Bh[7 * 128 * 128];
__device__ __align__(16) __nv_bfloat16 g_Bl[7 * 128 * 128];

// ---------------- utils ----------------
__device__ __forceinline__ float warp_sum(float v) {
#pragma unroll
    for (int o = 16; o; o >>= 1) v += __shfl_xor_sync(0xffffffffu, v, o);
    return v;
}

__device__ __forceinline__ float ex2(float x) {
    float y;
    asm("ex2.approx.ftz.f32 %0, %1;" : "=f"(y) : "f"(x));
    return y;
}

__device__ __forceinline__ uint32_t smem_u32(const void* p) {
    uint32_t a;
    asm("{ .reg .u64 t; cvta.to.shared.u64 t, %1; cvt.u32.u64 %0, t; }" : "=r"(a) : "l"(p));
    return a;
}

__device__ __forceinline__ void mma16816(float* d, uint32_t a0, uint32_t a1, uint32_t a2,
                                         uint32_t a3, uint32_t b0, uint32_t b1) {
    asm volatile(
        "mma.sync.aligned.m16n8k16.row.col.f32.bf16.bf16.f32 "
        "{%0,%1,%2,%3}, {%4,%5,%6,%7}, {%8,%9}, {%0,%1,%2,%3};"
        : "+f"(d[0]), "+f"(d[1]), "+f"(d[2]), "+f"(d[3])
        : "r"(a0), "r"(a1), "r"(a2), "r"(a3), "r"(b0), "r"(b1));
}

__device__ __forceinline__ void ldsm_x4(uint32_t& r0, uint32_t& r1, uint32_t& r2, uint32_t& r3,
                                        uint32_t addr) {
    asm volatile("ldmatrix.sync.aligned.m8n8.x4.shared.b16 {%0,%1,%2,%3}, [%4];"
                 : "=r"(r0), "=r"(r1), "=r"(r2), "=r"(r3) : "r"(addr));
}

// ---------------- preprocessing ----------------
__global__ void k_zero(int n) {
    int i = blockIdx.x * blockDim.x + threadIdx.x;
    if (i < n) { g_deg[i] = 0; g_cnt[i] = 0; }
}

__global__ void k_hist(const int* __restrict__ ei, int Ee) {
    int e = blockIdx.x * blockDim.x + threadIdx.x;
    if (e < Ee) atomicAdd(&g_deg[ei[Ee + e]], 1);
}

__global__ void k_scan1(int n) {
    __shared__ int ws[32];
    int i = blockIdx.x * 1024 + threadIdx.x;
    int lane = threadIdx.x & 31, wid = threadIdx.x >> 5;
    int v = (i < n) ? g_deg[i] : 0;
    int x = v;
#pragma unroll
    for (int o = 1; o < 32; o <<= 1) {
        int y = __shfl_up_sync(0xffffffffu, x, o);
        if (lane >= o) x += y;
    }
    if (lane == 31) ws[wid] = x;
    __syncthreads();
    if (wid == 0) {
        int y = ws[lane];
#pragma unroll
        for (int o = 1; o < 32; o <<= 1) {
            int z = __shfl_up_sync(0xffffffffu, y, o);
            if (lane >= o) y += z;
        }
        ws[lane] = y;
    }
    __syncthreads();
    int inc = x + (wid > 0 ? ws[wid - 1] : 0);
    if (i < n) g_off[i] = inc - v;
    if (threadIdx.x == 1023) g_bsum[blockIdx.x] = inc;
}

__global__ void k_scan2(int nb) {
    int lane = threadIdx.x;  // 32 threads
    int run = 0;
    for (int base = 0; base < nb; base += 32) {
        int idx = base + lane;
        int v = (idx < nb) ? g_bsum[idx] : 0;
        int x = v;
#pragma unroll
        for (int o = 1; o < 32; o <<= 1) {
            int y = __shfl_up_sync(0xffffffffu, x, o);
            if (lane >= o) x += y;
        }
        if (idx < nb) g_bsum[idx] = x - v + run;
        run += __shfl_sync(0xffffffffu, x, 31);
    }
    if (lane == 0) g_bsum[nb] = run;
}

__global__ void k_scan3(int n) {
    int i = blockIdx.x * 1024 + threadIdx.x;
    if (i < n) g_off[i] += g_bsum[blockIdx.x];
    if (i == 0) g_off[n] = g_bsum[gridDim.x];
}

__global__ void k_scatter(const int* __restrict__ ei, int Ee) {
    int e = blockIdx.x * blockDim.x + threadIdx.x;
    if (e >= Ee) return;
    int d = ei[Ee + e];
    int p = g_off[d] + atomicAdd(&g_cnt[d], 1);
    g_eid[p] = e;
}

__device__ __forceinline__ uint2 pack_half4(float4 v) {
    __half2 p0 = __floats2half2_rn(v.x, v.y);
    __half2 p1 = __floats2half2_rn(v.z, v.w);
    uint2 u;
    u.x = *reinterpret_cast<uint32_t*>(&p0);
    u.y = *reinterpret_cast<uint32_t*>(&p1);
    return u;
}

__global__ void k_sortfix(const int* __restrict__ ei, const float4* __restrict__ ea, int Nn) {
    int n = blockIdx.x * blockDim.x + threadIdx.x;
    if (n >= Nn) return;
    int st = g_off[n], en = g_off[n + 1];
    int d = en - st;
    if (d <= 0) return;
    if (d <= 192) {
        int a[192];
        for (int i = 0; i < d; i++) a[i] = g_eid[st + i];
        for (int i = 1; i < d; i++) {
            int key = a[i]; int j = i - 1;
            while (j >= 0 && a[j] > key) { a[j + 1] = a[j]; j--; }
            a[j + 1] = key;
        }
        for (int i = 0; i < d; i++) {
            int eid = a[i];
            g_srcS[st + i] = ei[eid];
            g_eaS2[st + i] = pack_half4(ea[eid]);
        }
    } else {
        for (int i = 0; i < d - 1; i++) {
            int mn = i;
            for (int j = i + 1; j < d; j++)
                if (g_eid[st + j] < g_eid[st + mn]) mn = j;
            int t = g_eid[st + i]; g_eid[st + i] = g_eid[st + mn]; g_eid[st + mn] = t;
        }
        for (int i = 0; i < d; i++) {
            int eid = g_eid[st + i];
            g_srcS[st + i] = ei[eid];
            g_eaS2[st + i] = pack_half4(ea[eid]);
        }
    }
}

// edge attention weights folded per layer (x log2e)
__global__ void k_prep_weh(const float* __restrict__ We, const float* __restrict__ aev) {
    int l = blockIdx.x;
    int t = threadIdx.x;  // 32
    int d = t >> 3, h = t & 7;
    float s = 0.f;
#pragma unroll
    for (int c = 0; c < 16; c++)
        s += We[l * 4 * HID + d * HID + h * 16 + c] * aev[l * HID + h * 16 + c];
    g_weh[l * 32 + d * 8 + h] = s * LOG2E;
}

// transpose + bf16-split weights
__global__ void k_prep_bsplit(const float* __restrict__ Wg, const float* __restrict__ W1) {
    int l = blockIdx.x;
    const float* W = (l < NLAYERS) ? (Wg + (size_t)l * HID * HID) : W1;
    int n = threadIdx.x;
    __nv_bfloat16* bh = g_Bh + (size_t)l * HID * HID;
    __nv_bfloat16* bl = g_Bl + (size_t)l * HID * HID;
    for (int k = 0; k < HID; k++) {
        float v = W[k * HID + n];
        __nv_bfloat16 hb = __float2bfloat16(v);
        float r = v - __bfloat162float(hb);
        bh[n * HID + k] = hb;
        bl[n * HID + k] = __float2bfloat16(r);
    }
}

// ---------------- input projection: h0 = LN(relu(x @ W_in + b_in)) ----------------
__global__ void k_input(const float* __restrict__ x, const float* __restrict__ Win,
                        const float* __restrict__ bin, const float* __restrict__ g,
                        const float* __restrict__ b, float* __restrict__ h0, int Nn) {
    __shared__ float Ws[16 * HID];
    for (int i = threadIdx.x; i < 16 * HID; i += blockDim.x) Ws[i] = Win[i];
    __syncthreads();
    int gw = (blockIdx.x * blockDim.x + threadIdx.x) >> 5;
    if (gw >= Nn) return;
    int lane = threadIdx.x & 31;
    float4 bv = ((const float4*)bin)[lane];
    float acc0 = bv.x, acc1 = bv.y, acc2 = bv.z, acc3 = bv.w;
#pragma unroll
    for (int k = 0; k < 16; k++) {
        float xv = __ldg(x + (size_t)gw * 16 + k);
        acc0 += xv * Ws[k * HID + lane * 4 + 0];
        acc1 += xv * Ws[k * HID + lane * 4 + 1];
        acc2 += xv * Ws[k * HID + lane * 4 + 2];
        acc3 += xv * Ws[k * HID + lane * 4 + 3];
    }
    float t0 = fmaxf(acc0, 0.f), t1 = fmaxf(acc1, 0.f), t2 = fmaxf(acc2, 0.f), t3 = fmaxf(acc3, 0.f);
    float sm = warp_sum(t0 + t1 + t2 + t3);
    float sq = warp_sum(t0 * t0 + t1 * t1 + t2 * t2 + t3 * t3);
    float mu = sm * (1.f / 128.f);
    float var = sq * (1.f / 128.f) - mu * mu;
    float rs = rsqrtf(var + 1e-5f);
    float4 gv = ((const float4*)g)[lane];
    float4 bbv = ((const float4*)b)[lane];
    float4 o;
    o.x = (t0 - mu) * rs * gv.x + bbv.x;
    o.y = (t1 - mu) * rs * gv.y + bbv.y;
    o.z = (t2 - mu) * rs * gv.z + bbv.z;
    o.w = (t3 - mu) * rs * gv.w + bbv.w;
    ((float4*)(h0 + (size_t)gw * HID))[lane] = o;
}

// ---------------- HMMA GEMM: C[M,128] = A[M,128] @ W[128,128] via bf16x3 split ----
// M-tile 64 (2 CTAs/SM), warp layout 2(M) x 4(N). Fragments via ldmatrix.x4.
// MODE 0: C -> fp16 hp, fused fp16 alpha_src + fp32 alpha_dst epilogue (x log2e)
// MODE 1: fused output head: out = relu(relu(C + b1) @ W2 + b2), OUT_DIM=3
#define RS 272
#define OFF_AHI 0
#define OFF_ALO 17408
#define OFF_BHI 34816
#define OFF_BLO 69632
#define OFF_ATT 104448
#define SM_TOT  105472

template <int MODE>
__global__ void __launch_bounds__(256, 2) k_mma(
    const float* __restrict__ A, const __nv_bfloat16* __restrict__ BhG,
    const __nv_bfloat16* __restrict__ BlG, const float* __restrict__ v1,
    const float* __restrict__ v2, __half* __restrict__ Ch,
    __half* __restrict__ oAS, float* __restrict__ oAD,
    const float* __restrict__ W2g, const float* __restrict__ b2g,
    float* __restrict__ outg, int M) {
    extern __shared__ char smem[];
    char* Ahi = smem + OFF_AHI;
    char* Alo = smem + OFF_ALO;
    char* Bhi = smem + OFF_BHI;
    char* Blo = smem + OFF_BLO;
    float* att = (float*)(smem + OFF_ATT);
    float* Cs = (float*)smem;  // reused after compute (row stride 132 floats)
    const int tid = threadIdx.x;
    const int m0 = blockIdx.x * 64;

    if (MODE == 0) {
        if (tid < 128) att[tid] = v1[tid] * LOG2E;
        else att[tid] = v2[tid - 128] * LOG2E;
    } else {
        if (tid < 128) att[tid] = v1[tid];
    }

    // ---- fill A (64 rows): fp32 -> bf16 hi/lo ----
#pragma unroll
    for (int it = 0; it < 4; it++) {
        int q = tid + it * 256;
        int r = q >> 4, w = q & 15;
        int m = m0 + r;
        float f[8];
        if (m < M) {
            const float* ar = A + (size_t)m * HID + w * 8;
            float4 x0 = *(const float4*)ar;
            float4 x1 = *(const float4*)(ar + 4);
            f[0] = x0.x; f[1] = x0.y; f[2] = x0.z; f[3] = x0.w;
            f[4] = x1.x; f[5] = x1.y; f[6] = x1.z; f[7] = x1.w;
        } else {
#pragma unroll
            for (int i = 0; i < 8; i++) f[i] = 0.f;
        }
        uint32_t hu[8], lu[8];
#pragma unroll
        for (int i = 0; i < 8; i++) {
            __nv_bfloat16 hb = __float2bfloat16(f[i]);
            float rr = f[i] - __bfloat162float(hb);
            hu[i] = (uint32_t)__bfloat16_as_ushort(hb);
            lu[i] = (uint32_t)__bfloat16_as_ushort(__float2bfloat16(rr));
        }
        uint4 ph, pl;
        ph.x = hu[0] | (hu[1] << 16); ph.y = hu[2] | (hu[3] << 16);
        ph.z = hu[4] | (hu[5] << 16); ph.w = hu[6] | (hu[7] << 16);
        pl.x = lu[0] | (lu[1] << 16); pl.y = lu[2] | (lu[3] << 16);
        pl.z = lu[4] | (lu[5] << 16); pl.w = lu[6] | (lu[7] << 16);
        *(uint4*)(Ahi + r * RS + w * 16) = ph;
        *(uint4*)(Alo + r * RS + w * 16) = pl;
    }
    // ---- fill B (pre-split bf16 [n][k], 256B rows, 128 rows) ----
#pragma unroll
    for (int it = 0; it < 8; it++) {
        int q = tid + it * 256;
        int r = q >> 4, w = q & 15;
        *(uint4*)(Bhi + r * RS + w * 16) = *(const uint4*)((const char*)BhG + r * 256 + w * 16);
        *(uint4*)(Blo + r * RS + w * 16) = *(const uint4*)((const char*)BlG + r * 256 + w * 16);
    }
    __syncthreads();

    const int wid = tid >> 5, lane = tid & 31;
    const int cq = lane & 3, gq = lane >> 2;
    const int mb = (wid & 1) * 32;
    const int nb = (wid >> 1) * 32;

    float acc[2][4][4];
#pragma unroll
    for (int a = 0; a < 2; a++)
#pragma unroll
        for (int j = 0; j < 4; j++)
#pragma unroll
            for (int i = 0; i < 4; i++) acc[a][j][i] = 0.f;

    const uint32_t sbase = smem_u32(smem);
    const int l7 = lane & 7;
    const uint32_t aAddr = sbase + OFF_AHI +
        (uint32_t)(mb + l7 + ((lane >> 3) & 1) * 8) * RS + ((lane >> 4) & 1) * 16;
    const uint32_t bAddr = sbase + OFF_BHI +
        (uint32_t)(nb + ((lane >> 4) & 1) * 8 + l7) * RS + ((lane >> 3) & 1) * 16;
    const uint32_t ALO_D = OFF_ALO - OFF_AHI;
    const uint32_t BLO_D = OFF_BLO - OFF_BHI;

#pragma unroll
    for (int kc = 0; kc < 8; kc++) {
        const uint32_t kby = kc * 32;
        uint32_t ah[2][4], al[2][4], bh[4][2], bl[4][2];
        ldsm_x4(ah[0][0], ah[0][1], ah[0][2], ah[0][3], aAddr + kby);
        ldsm_x4(ah[1][0], ah[1][1], ah[1][2], ah[1][3], aAddr + 16 * RS + kby);
        ldsm_x4(al[0][0], al[0][1], al[0][2], al[0][3], aAddr + ALO_D + kby);
        ldsm_x4(al[1][0], al[1][1], al[1][2], al[1][3], aAddr + ALO_D + 16 * RS + kby);
        ldsm_x4(bh[0][0], bh[0][1], bh[1][0], bh[1][1], bAddr + kby);
        ldsm_x4(bh[2][0], bh[2][1], bh[3][0], bh[3][1], bAddr + 16 * RS + kby);
        ldsm_x4(bl[0][0], bl[0][1], bl[1][0], bl[1][1], bAddr + BLO_D + kby);
        ldsm_x4(bl[2][0], bl[2][1], bl[3][0], bl[3][1], bAddr + BLO_D + 16 * RS + kby);
#pragma unroll
        for (int j = 0; j < 4; j++) {
#pragma unroll
            for (int mt = 0; mt < 2; mt++) {
                mma16816(acc[mt][j], ah[mt][0], ah[mt][1], ah[mt][2], ah[mt][3],
                         bh[j][0], bh[j][1]);
                mma16816(acc[mt][j], al[mt][0], al[mt][1], al[mt][2], al[mt][3],
                         bh[j][0], bh[j][1]);
                mma16816(acc[mt][j], ah[mt][0], ah[mt][1], ah[mt][2], ah[mt][3],
                         bl[j][0], bl[j][1]);
            }
        }
    }

    // ---- fused alpha epilogue (MODE 0): alpha_src -> fp16, alpha_dst -> fp32 ----
    if (MODE == 0) {
        float sAS[2][2][2], sAD[2][2][2];
#pragma unroll
        for (int a = 0; a < 2; a++)
#pragma unroll
            for (int hf = 0; hf < 2; hf++)
#pragma unroll
                for (int h = 0; h < 2; h++) { sAS[a][hf][h] = 0.f; sAD[a][hf][h] = 0.f; }
#pragma unroll
        for (int mt = 0; mt < 2; mt++)
#pragma unroll
            for (int j = 0; j < 4; j++) {
                int hl = j >> 1;
                int col = nb + j * 8 + 2 * cq;
                float w0 = att[col], w1 = att[col + 1];
                float u0 = att[128 + col], u1 = att[128 + col + 1];
                sAS[mt][0][hl] += acc[mt][j][0] * w0 + acc[mt][j][1] * w1;
                sAS[mt][1][hl] += acc[mt][j][2] * w0 + acc[mt][j][3] * w1;
                sAD[mt][0][hl] += acc[mt][j][0] * u0 + acc[mt][j][1] * u1;
                sAD[mt][1][hl] += acc[mt][j][2] * u0 + acc[mt][j][3] * u1;
            }
#pragma unroll
        for (int mt = 0; mt < 2; mt++)
#pragma unroll
            for (int hf = 0; hf < 2; hf++)
#pragma unroll
                for (int h = 0; h < 2; h++) {
                    float v = sAS[mt][hf][h];
                    v += __shfl_xor_sync(0xffffffffu, v, 1);
                    v += __shfl_xor_sync(0xffffffffu, v, 2);
                    sAS[mt][hf][h] = v;
                    float u = sAD[mt][hf][h];
                    u += __shfl_xor_sync(0xffffffffu, u, 1);
                    u += __shfl_xor_sync(0xffffffffu, u, 2);
                    sAD[mt][hf][h] = u;
                }
        if (cq == 0) {
#pragma unroll
            for (int mt = 0; mt < 2; mt++)
#pragma unroll
                for (int hf = 0; hf < 2; hf++) {
                    int r = m0 + mb + mt * 16 + hf * 8 + gq;
                    if (r < M) {
                        __half2 p = __floats2half2_rn(sAS[mt][hf][0], sAS[mt][hf][1]);
                        *(uint32_t*)(oAS + (size_t)r * 8 + (nb >> 4)) =
                            *reinterpret_cast<uint32_t*>(&p);
                        *(float2*)(oAD + (size_t)r * 8 + (nb >> 4)) =
                            make_float2(sAD[mt][hf][0], sAD[mt][hf][1]);
                    }
                }
        }
    }

    // ---- stage C in SMEM ----
    __syncthreads();
#pragma unroll
    for (int mt = 0; mt < 2; mt++)
#pragma unroll
        for (int j = 0; j < 4; j++) {
            int row = mb + mt * 16 + gq;
            int col = nb + j * 8 + 2 * cq;
            *(float2*)(Cs + row * 132 + col) = make_float2(acc[mt][j][0], acc[mt][j][1]);
            *(float2*)(Cs + (row + 8) * 132 + col) = make_float2(acc[mt][j][2], acc[mt][j][3]);
        }
    __syncthreads();

    if (MODE == 0) {
        // write hp as fp16, coalesced
#pragma unroll
        for (int it = 0; it < 8; it++) {
            int q = tid + it * 256;
            int r = q >> 5, w = q & 31;
            int m = m0 + r;
            if (m < M) {
                float4 v = *(float4*)(Cs + r * 132 + w * 4);
                __half2 p0 = __floats2half2_rn(v.x, v.y);
                __half2 p1 = __floats2half2_rn(v.z, v.w);
                uint2 u;
                u.x = *reinterpret_cast<uint32_t*>(&p0);
                u.y = *reinterpret_cast<uint32_t*>(&p1);
                *(uint2*)(Ch + (size_t)m * HID + w * 4) = u;
            }
        }
    } else {
        // fused output head: out[m] = relu( relu(C[m]+b1) @ W2 + b2 ), OUT_DIM=3
        int r = tid >> 2;       // row 0..63
        int qq = tid & 3;       // channel quarter
        int m = m0 + r;
        float p0 = 0.f, p1 = 0.f, p2 = 0.f;
        const float* cr = Cs + r * 132 + qq * 32;
        const float* ar = att + qq * 32;
        const float* w2 = W2g + qq * 32 * 3;
#pragma unroll
        for (int i = 0; i < 32; i++) {
            float v = fmaxf(cr[i] + ar[i], 0.f);
            p0 = fmaf(v, __ldg(&w2[i * 3 + 0]), p0);
            p1 = fmaf(v, __ldg(&w2[i * 3 + 1]), p1);
            p2 = fmaf(v, __ldg(&w2[i * 3 + 2]), p2);
        }
        p0 += __shfl_xor_sync(0xffffffffu, p0, 1);
        p0 += __shfl_xor_sync(0xffffffffu, p0, 2);
        p1 += __shfl_xor_sync(0xffffffffu, p1, 1);
        p1 += __shfl_xor_sync(0xffffffffu, p1, 2);
        p2 += __shfl_xor_sync(0xffffffffu, p2, 1);
        p2 += __shfl_xor_sync(0xffffffffu, p2, 2);
        if (qq == 0 && m < M) {
            outg[(size_t)m * 3 + 0] = fmaxf(p0 + __ldg(&b2g[0]), 0.f);
            outg[(size_t)m * 3 + 1] = fmaxf(p1 + __ldg(&b2g[1]), 0.f);
            outg[(size_t)m * 3 + 2] = fmaxf(p2 + __ldg(&b2g[2]), 0.f);
        }
    }
}

// ---------------- fused attention + aggregation + residual + LN (R7 champion) ----
// Half-warp per edge; each lane covers 8 channels; 1-ahead (src,ea) prefetch.
// 64-thread blocks: finest retirement granularity without occupancy loss.
__global__ void k_gat_edge(const float* __restrict__ hcur, const float* __restrict__ weh_l,
                           const float* __restrict__ bgl, const float* __restrict__ lng,
                           const float* __restrict__ lnb, float* __restrict__ hnext, int Nn) {
    int gw = (blockIdx.x * blockDim.x + threadIdx.x) >> 5;
    if (gw >= Nn) return;
    int lane = threadIdx.x & 31;
    int half = lane >> 4;
    int sl = lane & 15;      // channel group: 8*sl .. 8*sl+7
    int hh = sl >> 1;        // head
    float adv = __ldg(&g_ad[(size_t)gw * 8 + hh]);
    float w0 = __ldg(&weh_l[0 * 8 + hh]);
    float w1 = __ldg(&weh_l[1 * 8 + hh]);
    float w2 = __ldg(&weh_l[2 * 8 + hh]);
    float w3 = __ldg(&weh_l[3 * 8 + hh]);
    int s0 = g_off[gw], s1 = g_off[gw + 1];
    int d = s1 - s0;

    float acc[8];
#pragma unroll
    for (int q = 0; q < 8; q++) acc[q] = 0.f;
    float den = 0.f;

    int i = half;
    int sP = 0; uint2 eaP = make_uint2(0, 0);
    if (i < d) { sP = __ldg(&g_srcS[s0 + i]); eaP = g_eaS2[s0 + i]; }
    for (; i < d; i += 2) {
        int s = sP; uint2 eau = eaP;
        if (i + 2 < d) { sP = __ldg(&g_srcS[s0 + i + 2]); eaP = g_eaS2[s0 + i + 2]; }
        float asv = __half2float(g_as16[(size_t)s * 8 + hh]);
        float2 f01 = __half22float2(*reinterpret_cast<__half2*>(&eau.x));
        float2 f23 = __half22float2(*reinterpret_cast<__half2*>(&eau.y));
        float al = asv + adv + f01.x * w0 + f01.y * w1 + f23.x * w2 + f23.y * w3;
        al = fmaxf(al, 0.2f * al);
        float a = ex2(al);
        den += a;
        uint4 hv = *(const uint4*)(g_hp16 + (size_t)s * HID + sl * 8);
        __half2* hp2 = reinterpret_cast<__half2*>(&hv);
#pragma unroll
        for (int q = 0; q < 4; q++) {
            float2 f = __half22float2(hp2[q]);
            acc[2 * q] = fmaf(a, f.x, acc[2 * q]);
            acc[2 * q + 1] = fmaf(a, f.y, acc[2 * q + 1]);
        }
    }

    // merge even/odd halves (fixed order)
#pragma unroll
    for (int q = 0; q < 8; q++) acc[q] += __shfl_xor_sync(0xffffffffu, acc[q], 16);
    den += __shfl_xor_sync(0xffffffffu, den, 16);

    float r = 1.f / (den + 1e-16f);
    const float4* hcr = (const float4*)(hcur + (size_t)gw * HID + sl * 8);
    float4 hc0 = hcr[0], hc1 = hcr[1];
    const float4* bgr = (const float4*)(bgl + sl * 8);
    float4 bg0 = bgr[0], bg1 = bgr[1];
    float t8[8];
    t8[0] = hc0.x + acc[0] * r + bg0.x;
    t8[1] = hc0.y + acc[1] * r + bg0.y;
    t8[2] = hc0.z + acc[2] * r + bg0.z;
    t8[3] = hc0.w + acc[3] * r + bg0.w;
    t8[4] = hc1.x + acc[4] * r + bg1.x;
    t8[5] = hc1.y + acc[5] * r + bg1.y;
    t8[6] = hc1.z + acc[6] * r + bg1.z;
    t8[7] = hc1.w + acc[7] * r + bg1.w;
    float sm = 0.f, sq = 0.f;
#pragma unroll
    for (int q = 0; q < 8; q++) { sm += t8[q]; sq += t8[q] * t8[q]; }
    sm = warp_sum(sm);  // both halves duplicate -> 2x channel sum
    sq = warp_sum(sq);
    float mu = sm * (1.f / 256.f);
    float var = sq * (1.f / 256.f) - mu * mu;
    float rs = rsqrtf(var + 1e-5f);
    if (half == 0) {
        const float4* gr = (const float4*)(lng + sl * 8);
        const float4* br = (const float4*)(lnb + sl * 8);
        float4 g0 = gr[0], g1 = gr[1];
        float4 b0 = br[0], b1 = br[1];
        float4 o0, o1;
        o0.x = (t8[0] - mu) * rs * g0.x + b0.x;
        o0.y = (t8[1] - mu) * rs * g0.y + b0.y;
        o0.z = (t8[2] - mu) * rs * g0.z + b0.z;
        o0.w = (t8[3] - mu) * rs * g0.w + b0.w;
        o1.x = (t8[4] - mu) * rs * g1.x + b1.x;
        o1.y = (t8[5] - mu) * rs * g1.y + b1.y;
        o1.z = (t8[6] - mu) * rs * g1.z + b1.z;
        o1.w = (t8[7] - mu) * rs * g1.w + b1.w;
        float4* outp = (float4*)(hnext + (size_t)gw * HID + sl * 8);
        outp[0] = o0;
        outp[1] = o1;
    }
}

// ---------------- launch ----------------
extern "C" void kernel_launch(void* const* d_in, const int* in_sizes, int n_in,
                              void* d_out, int out_size) {
    const float* x = (const float*)d_in[0];
    const int* ei = (const int*)d_in[1];
    const float* ea = (const float*)d_in[2];
    const float* W_in = (const float*)d_in[3];
    const float* b_in = (const float*)d_in[4];
    const float* ln_in_g = (const float*)d_in[5];
    const float* ln_in_b = (const float*)d_in[6];
    const float* Wg = (const float*)d_in[7];
    const float* att_src = (const float*)d_in[8];
    const float* att_dst = (const float*)d_in[9];
    const float* We = (const float*)d_in[10];
    const float* att_edge = (const float*)d_in[11];
    const float* bg = (const float*)d_in[12];
    const float* ln_g = (const float*)d_in[13];
    const float* ln_b = (const float*)d_in[14];
    const float* W1 = (const float*)d_in[15];
    const float* b1 = (const float*)d_in[16];
    const float* W2 = (const float*)d_in[17];
    const float* b2 = (const float*)d_in[18];

    int Nn = in_sizes[0] / 16;   // 100000
    int Ee = in_sizes[2] / 4;    // 1600000

    float *hA, *hB, *weh, *ad;
    __half *hp16, *as16;
    __nv_bfloat16 *Bh, *Bl;
    cudaGetSymbolAddress((void**)&hA, g_hA);
    cudaGetSymbolAddress((void**)&hB, g_hB);
    cudaGetSymbolAddress((void**)&hp16, g_hp16);
    cudaGetSymbolAddress((void**)&weh, g_weh);
    cudaGetSymbolAddress((void**)&as16, g_as16);
    cudaGetSymbolAddress((void**)&ad, g_ad);
    cudaGetSymbolAddress((void**)&Bh, g_Bh);
    cudaGetSymbolAddress((void**)&Bl, g_Bl);

    cudaFuncSetAttribute(k_mma<0>, cudaFuncAttributeMaxDynamicSharedMemorySize, SM_TOT);
    cudaFuncSetAttribute(k_mma<1>, cudaFuncAttributeMaxDynamicSharedMemorySize, SM_TOT);

    int nwb = (Nn + 7) / 8;       // 256-thread blocks (input proj)
    int neb = (Nn + 1) / 2;       // 64-thread blocks (edge kernel)
    int mb = (Nn + 63) / 64;

    // ---- independent prep first, layer-0 GEMM at launch position 4 (ncu target) ----
    k_prep_bsplit<<<NLAYERS + 1, 128>>>(Wg, W1);                               // 1
    k_input<<<nwb, 256>>>(x, W_in, b_in, ln_in_g, ln_in_b, hA, Nn);            // 2
    k_prep_weh<<<NLAYERS, 32>>>(We, att_edge);                                 // 3
    k_mma<0><<<mb, 256, SM_TOT>>>(hA, Bh, Bl, att_src, att_dst,                // 4 <- ncu target
                                  hp16, as16, ad, nullptr, nullptr, nullptr, Nn);

    // ---- CSR preprocessing ----
    k_zero<<<(Nn + 255) / 256, 256>>>(Nn);
    k_hist<<<(Ee + 255) / 256, 256>>>(ei, Ee);
    int nb = (Nn + 1023) / 1024;
    k_scan1<<<nb, 1024>>>(Nn);
    k_scan2<<<1, 32>>>(nb);
    k_scan3<<<nb, 1024>>>(Nn);
    k_scatter<<<(Ee + 255) / 256, 256>>>(ei, Ee);
    k_sortfix<<<(Nn + 255) / 256, 256>>>(ei, (const float4*)ea, Nn);

    // ---- GAT layers (layer 0 GEMM already done) ----
    float* hcur = hA;
    float* hnxt = hB;
    for (int l = 0; l < NLAYERS; l++) {
        if (l > 0) {
            k_mma<0><<<mb, 256, SM_TOT>>>(hcur, Bh + (size_t)l * HID * HID,
                                          Bl + (size_t)l * HID * HID,
                                          att_src + l * HID, att_dst + l * HID,
                                          hp16, as16, ad, nullptr, nullptr, nullptr, Nn);
        }
        k_gat_edge<<<neb, 64>>>(hcur, weh + l * 32, bg + l * HID,
                                ln_g + l * HID, ln_b + l * HID, hnxt, Nn);
        float* t = hcur; hcur = hnxt; hnxt = t;
    }

    // ---- output head (fully fused into k_mma<1>) ----
    k_mma<1><<<mb, 256, SM_TOT>>>(hcur, Bh + (size_t)NLAYERS * HID * HID,
                                  Bl + (size_t)NLAYERS * HID * HID,
                                  b1, b1, nullptr, nullptr, nullptr,
                                  W2, b2, (float*)d_out, Nn);
}

// round 16
// speedup vs baseline: 1.0985x; 1.0322x over previous
#include <cuda_runtime.h>
#include <cuda_bf16.h>
#include <cuda_fp16.h>
#include <cstdint>

#define NMAX 100000
#define EMAX 1600000
#define HID 128
#define HEADS 8
#define NLAYERS 6
#define LOG2E 1.44269504f
#define GEMM_GRID 296

// ---------------- scratch (device globals; no allocation allowed) ----------------
__device__ __align__(16) float g_hA[(size_t)NMAX * HID];
__device__ __align__(16) float g_hB[(size_t)NMAX * HID];
__device__ __align__(16) __half g_hp16[(size_t)NMAX * HID];    // fp16 messages
__device__ __align__(16) __half g_as16[(size_t)NMAX * HEADS];  // fp16 alpha_src (x log2e)
__device__ __align__(16) float g_ad[(size_t)NMAX * HEADS];     // fp32 alpha_dst (x log2e)
__device__ int g_off[NMAX + 1];
__device__ int g_deg[NMAX];
__device__ int g_cnt[NMAX];
__device__ int g_bsum[256];
__device__ int g_eid[EMAX];
__device__ int g_srcS[EMAX];
__device__ __align__(8) uint2 g_eaS2[EMAX];  // half4 edge attrs, dst-sorted
__device__ float g_weh[NLAYERS * 4 * HEADS]; // x log2e
// pre-split transposed weights: [7][n=128][k=128] bf16 (6 GAT layers + W1)
__device__ __align__(16) __nv_bfloat16 g_Bh[7 * 128 * 128];
__device__ __align__(16) __nv_bfloat16 g_Bl[7 * 128 * 128];

// ---------------- utils ----------------
__device__ __forceinline__ float warp_sum(float v) {
#pragma unroll
    for (int o = 16; o; o >>= 1) v += __shfl_xor_sync(0xffffffffu, v, o);
    return v;
}

__device__ __forceinline__ float ex2(float x) {
    float y;
    asm("ex2.approx.ftz.f32 %0, %1;" : "=f"(y) : "f"(x));
    return y;
}

__device__ __forceinline__ uint32_t smem_u32(const void* p) {
    uint32_t a;
    asm("{ .reg .u64 t; cvta.to.shared.u64 t, %1; cvt.u32.u64 %0, t; }" : "=r"(a) : "l"(p));
    return a;
}

__device__ __forceinline__ void mma16816(float* d, uint32_t a0, uint32_t a1, uint32_t a2,
                                         uint32_t a3, uint32_t b0, uint32_t b1) {
    asm volatile(
        "mma.sync.aligned.m16n8k16.row.col.f32.bf16.bf16.f32 "
        "{%0,%1,%2,%3}, {%4,%5,%6,%7}, {%8,%9}, {%0,%1,%2,%3};"
        : "+f"(d[0]), "+f"(d[1]), "+f"(d[2]), "+f"(d[3])
        : "r"(a0), "r"(a1), "r"(a2), "r"(a3), "r"(b0), "r"(b1));
}

__device__ __forceinline__ void ldsm_x4(uint32_t& r0, uint32_t& r1, uint32_t& r2, uint32_t& r3,
                                        uint32_t addr) {
    asm volatile("ldmatrix.sync.aligned.m8n8.x4.shared.b16 {%0,%1,%2,%3}, [%4];"
                 : "=r"(r0), "=r"(r1), "=r"(r2), "=r"(r3) : "r"(addr));
}

// ---------------- preprocessing ----------------
__global__ void k_zero(int n) {
    int i = blockIdx.x * blockDim.x + threadIdx.x;
    if (i < n) { g_deg[i] = 0; g_cnt[i] = 0; }
}

__global__ void k_hist(const int* __restrict__ ei, int Ee) {
    int e = blockIdx.x * blockDim.x + threadIdx.x;
    if (e < Ee) atomicAdd(&g_deg[ei[Ee + e]], 1);
}

__global__ void k_scan1(int n) {
    __shared__ int ws[32];
    int i = blockIdx.x * 1024 + threadIdx.x;
    int lane = threadIdx.x & 31, wid = threadIdx.x >> 5;
    int v = (i < n) ? g_deg[i] : 0;
    int x = v;
#pragma unroll
    for (int o = 1; o < 32; o <<= 1) {
        int y = __shfl_up_sync(0xffffffffu, x, o);
        if (lane >= o) x += y;
    }
    if (lane == 31) ws[wid] = x;
    __syncthreads();
    if (wid == 0) {
        int y = ws[lane];
#pragma unroll
        for (int o = 1; o < 32; o <<= 1) {
            int z = __shfl_up_sync(0xffffffffu, y, o);
            if (lane >= o) y += z;
        }
        ws[lane] = y;
    }
    __syncthreads();
    int inc = x + (wid > 0 ? ws[wid - 1] : 0);
    if (i < n) g_off[i] = inc - v;
    if (threadIdx.x == 1023) g_bsum[blockIdx.x] = inc;
}

__global__ void k_scan2(int nb) {
    int lane = threadIdx.x;  // 32 threads
    int run = 0;
    for (int base = 0; base < nb; base += 32) {
        int idx = base + lane;
        int v = (idx < nb) ? g_bsum[idx] : 0;
        int x = v;
#pragma unroll
        for (int o = 1; o < 32; o <<= 1) {
            int y = __shfl_up_sync(0xffffffffu, x, o);
            if (lane >= o) x += y;
        }
        if (idx < nb) g_bsum[idx] = x - v + run;
        run += __shfl_sync(0xffffffffu, x, 31);
    }
    if (lane == 0) g_bsum[nb] = run;
}

__global__ void k_scan3(int n) {
    int i = blockIdx.x * 1024 + threadIdx.x;
    if (i < n) g_off[i] += g_bsum[blockIdx.x];
    if (i == 0) g_off[n] = g_bsum[gridDim.x];
}

__global__ void k_scatter(const int* __restrict__ ei, int Ee) {
    int e = blockIdx.x * blockDim.x + threadIdx.x;
    if (e >= Ee) return;
    int d = ei[Ee + e];
    int p = g_off[d] + atomicAdd(&g_cnt[d], 1);
    g_eid[p] = e;
}

__device__ __forceinline__ uint2 pack_half4(float4 v) {
    __half2 p0 = __floats2half2_rn(v.x, v.y);
    __half2 p1 = __floats2half2_rn(v.z, v.w);
    uint2 u;
    u.x = *reinterpret_cast<uint32_t*>(&p0);
    u.y = *reinterpret_cast<uint32_t*>(&p1);
    return u;
}

__global__ void k_sortfix(const int* __restrict__ ei, const float4* __restrict__ ea, int Nn) {
    int n = blockIdx.x * blockDim.x + threadIdx.x;
    if (n >= Nn) return;
    int st = g_off[n], en = g_off[n + 1];
    int d = en - st;
    if (d <= 0) return;
    if (d <= 192) {
        int a[192];
        for (int i = 0; i < d; i++) a[i] = g_eid[st + i];
        for (int i = 1; i < d; i++) {
            int key = a[i]; int j = i - 1;
            while (j >= 0 && a[j] > key) { a[j + 1] = a[j]; j--; }
            a[j + 1] = key;
        }
        for (int i = 0; i < d; i++) {
            int eid = a[i];
            g_srcS[st + i] = ei[eid];
            g_eaS2[st + i] = pack_half4(ea[eid]);
        }
    } else {
        for (int i = 0; i < d - 1; i++) {
            int mn = i;
            for (int j = i + 1; j < d; j++)
                if (g_eid[st + j] < g_eid[st + mn]) mn = j;
            int t = g_eid[st + i]; g_eid[st + i] = g_eid[st + mn]; g_eid[st + mn] = t;
        }
        for (int i = 0; i < d; i++) {
            int eid = g_eid[st + i];
            g_srcS[st + i] = ei[eid];
            g_eaS2[st + i] = pack_half4(ea[eid]);
        }
    }
}

// edge attention weights folded per layer (x log2e)
__global__ void k_prep_weh(const float* __restrict__ We, const float* __restrict__ aev) {
    int l = blockIdx.x;
    int t = threadIdx.x;  // 32
    int d = t >> 3, h = t & 7;
    float s = 0.f;
#pragma unroll
    for (int c = 0; c < 16; c++)
        s += We[l * 4 * HID + d * HID + h * 16 + c] * aev[l * HID + h * 16 + c];
    g_weh[l * 32 + d * 8 + h] = s * LOG2E;
}

// transpose + bf16-split weights
__global__ void k_prep_bsplit(const float* __restrict__ Wg, const float* __restrict__ W1) {
    int l = blockIdx.x;
    const float* W = (l < NLAYERS) ? (Wg + (size_t)l * HID * HID) : W1;
    int n = threadIdx.x;
    __nv_bfloat16* bh = g_Bh + (size_t)l * HID * HID;
    __nv_bfloat16* bl = g_Bl + (size_t)l * HID * HID;
    for (int k = 0; k < HID; k++) {
        float v = W[k * HID + n];
        __nv_bfloat16 hb = __float2bfloat16(v);
        float r = v - __bfloat162float(hb);
        bh[n * HID + k] = hb;
        bl[n * HID + k] = __float2bfloat16(r);
    }
}

// ---------------- input projection: h0 = LN(relu(x @ W_in + b_in)) ----------------
__global__ void k_input(const float* __restrict__ x, const float* __restrict__ Win,
                        const float* __restrict__ bin, const float* __restrict__ g,
                        const float* __restrict__ b, float* __restrict__ h0, int Nn) {
    __shared__ float Ws[16 * HID];
    for (int i = threadIdx.x; i < 16 * HID; i += blockDim.x) Ws[i] = Win[i];
    __syncthreads();
    int gw = (blockIdx.x * blockDim.x + threadIdx.x) >> 5;
    if (gw >= Nn) return;
    int lane = threadIdx.x & 31;
    float4 bv = ((const float4*)bin)[lane];
    float acc0 = bv.x, acc1 = bv.y, acc2 = bv.z, acc3 = bv.w;
#pragma unroll
    for (int k = 0; k < 16; k++) {
        float xv = __ldg(x + (size_t)gw * 16 + k);
        acc0 += xv * Ws[k * HID + lane * 4 + 0];
        acc1 += xv * Ws[k * HID + lane * 4 + 1];
        acc2 += xv * Ws[k * HID + lane * 4 + 2];
        acc3 += xv * Ws[k * HID + lane * 4 + 3];
    }
    float t0 = fmaxf(acc0, 0.f), t1 = fmaxf(acc1, 0.f), t2 = fmaxf(acc2, 0.f), t3 = fmaxf(acc3, 0.f);
    float sm = warp_sum(t0 + t1 + t2 + t3);
    float sq = warp_sum(t0 * t0 + t1 * t1 + t2 * t2 + t3 * t3);
    float mu = sm * (1.f / 128.f);
    float var = sq * (1.f / 128.f) - mu * mu;
    float rs = rsqrtf(var + 1e-5f);
    float4 gv = ((const float4*)g)[lane];
    float4 bbv = ((const float4*)b)[lane];
    float4 o;
    o.x = (t0 - mu) * rs * gv.x + bbv.x;
    o.y = (t1 - mu) * rs * gv.y + bbv.y;
    o.z = (t2 - mu) * rs * gv.z + bbv.z;
    o.w = (t3 - mu) * rs * gv.w + bbv.w;
    ((float4*)(h0 + (size_t)gw * HID))[lane] = o;
}

// ---------------- persistent HMMA GEMM: C[M,128] = A[M,128] @ W[128,128], bf16x3 ----
// Grid = GEMM_GRID (2 CTAs/SM). B loaded ONCE per CTA; loop over M-tiles.
// Cs (C staging) fits inside the A hi/lo region, so B stays resident.
// MODE 0: C -> fp16 hp, fused fp16 alpha_src + fp32 alpha_dst epilogue (x log2e)
// MODE 1: fused output head: out = relu(relu(C + b1) @ W2 + b2), OUT_DIM=3
#define RS 272
#define OFF_AHI 0
#define OFF_ALO 17408
#define OFF_BHI 34816
#define OFF_BLO 69632
#define OFF_ATT 104448
#define SM_TOT  105472

template <int MODE>
__global__ void __launch_bounds__(256, 2) k_mma(
    const float* __restrict__ A, const __nv_bfloat16* __restrict__ BhG,
    const __nv_bfloat16* __restrict__ BlG, const float* __restrict__ v1,
    const float* __restrict__ v2, __half* __restrict__ Ch,
    __half* __restrict__ oAS, float* __restrict__ oAD,
    const float* __restrict__ W2g, const float* __restrict__ b2g,
    float* __restrict__ outg, int M) {
    extern __shared__ char smem[];
    char* Ahi = smem + OFF_AHI;
    char* Alo = smem + OFF_ALO;
    char* Bhi = smem + OFF_BHI;
    char* Blo = smem + OFF_BLO;
    float* att = (float*)(smem + OFF_ATT);
    float* Cs = (float*)smem;  // staging, lives inside A region (33792B < 34816B)
    const int tid = threadIdx.x;
    const int mtiles = (M + 63) >> 6;

    if (MODE == 0) {
        if (tid < 128) att[tid] = v1[tid] * LOG2E;
        else att[tid] = v2[tid - 128] * LOG2E;
    } else {
        if (tid < 128) att[tid] = v1[tid];
    }

    // ---- fill B ONCE (pre-split bf16 [n][k], 256B rows, 128 rows) ----
#pragma unroll
    for (int it = 0; it < 8; it++) {
        int q = tid + it * 256;
        int r = q >> 4, w = q & 15;
        *(uint4*)(Bhi + r * RS + w * 16) = *(const uint4*)((const char*)BhG + r * 256 + w * 16);
        *(uint4*)(Blo + r * RS + w * 16) = *(const uint4*)((const char*)BlG + r * 256 + w * 16);
    }

    const int wid = tid >> 5, lane = tid & 31;
    const int cq = lane & 3, gq = lane >> 2;
    const int mb = (wid & 1) * 32;
    const int nb = (wid >> 1) * 32;

    const uint32_t sbase = smem_u32(smem);
    const int l7 = lane & 7;
    const uint32_t aAddr = sbase + OFF_AHI +
        (uint32_t)(mb + l7 + ((lane >> 3) & 1) * 8) * RS + ((lane >> 4) & 1) * 16;
    const uint32_t bAddr = sbase + OFF_BHI +
        (uint32_t)(nb + ((lane >> 4) & 1) * 8 + l7) * RS + ((lane >> 3) & 1) * 16;
    const uint32_t ALO_D = OFF_ALO - OFF_AHI;
    const uint32_t BLO_D = OFF_BLO - OFF_BHI;

    for (int tile = blockIdx.x; tile < mtiles; tile += gridDim.x) {
        const int m0 = tile * 64;

        // ---- fill A (64 rows): fp32 -> bf16 hi/lo ----
#pragma unroll
        for (int it = 0; it < 4; it++) {
            int q = tid + it * 256;
            int r = q >> 4, w = q & 15;
            int m = m0 + r;
            float f[8];
            if (m < M) {
                const float* ar = A + (size_t)m * HID + w * 8;
                float4 x0 = *(const float4*)ar;
                float4 x1 = *(const float4*)(ar + 4);
                f[0] = x0.x; f[1] = x0.y; f[2] = x0.z; f[3] = x0.w;
                f[4] = x1.x; f[5] = x1.y; f[6] = x1.z; f[7] = x1.w;
            } else {
#pragma unroll
                for (int i = 0; i < 8; i++) f[i] = 0.f;
            }
            uint32_t hu[8], lu[8];
#pragma unroll
            for (int i = 0; i < 8; i++) {
                __nv_bfloat16 hb = __float2bfloat16(f[i]);
                float rr = f[i] - __bfloat162float(hb);
                hu[i] = (uint32_t)__bfloat16_as_ushort(hb);
                lu[i] = (uint32_t)__bfloat16_as_ushort(__float2bfloat16(rr));
            }
            uint4 ph, pl;
            ph.x = hu[0] | (hu[1] << 16); ph.y = hu[2] | (hu[3] << 16);
            ph.z = hu[4] | (hu[5] << 16); ph.w = hu[6] | (hu[7] << 16);
            pl.x = lu[0] | (lu[1] << 16); pl.y = lu[2] | (lu[3] << 16);
            pl.z = lu[4] | (lu[5] << 16); pl.w = lu[6] | (lu[7] << 16);
            *(uint4*)(Ahi + r * RS + w * 16) = ph;
            *(uint4*)(Alo + r * RS + w * 16) = pl;
        }
        __syncthreads();

        float acc[2][4][4];
#pragma unroll
        for (int a = 0; a < 2; a++)
#pragma unroll
            for (int j = 0; j < 4; j++)
#pragma unroll
                for (int i = 0; i < 4; i++) acc[a][j][i] = 0.f;

#pragma unroll
        for (int kc = 0; kc < 8; kc++) {
            const uint32_t kby = kc * 32;
            uint32_t ah[2][4], al[2][4], bh[4][2], bl[4][2];
            ldsm_x4(ah[0][0], ah[0][1], ah[0][2], ah[0][3], aAddr + kby);
            ldsm_x4(ah[1][0], ah[1][1], ah[1][2], ah[1][3], aAddr + 16 * RS + kby);
            ldsm_x4(al[0][0], al[0][1], al[0][2], al[0][3], aAddr + ALO_D + kby);
            ldsm_x4(al[1][0], al[1][1], al[1][2], al[1][3], aAddr + ALO_D + 16 * RS + kby);
            ldsm_x4(bh[0][0], bh[0][1], bh[1][0], bh[1][1], bAddr + kby);
            ldsm_x4(bh[2][0], bh[2][1], bh[3][0], bh[3][1], bAddr + 16 * RS + kby);
            ldsm_x4(bl[0][0], bl[0][1], bl[1][0], bl[1][1], bAddr + BLO_D + kby);
            ldsm_x4(bl[2][0], bl[2][1], bl[3][0], bl[3][1], bAddr + BLO_D + 16 * RS + kby);
#pragma unroll
            for (int j = 0; j < 4; j++) {
#pragma unroll
                for (int mt = 0; mt < 2; mt++) {
                    mma16816(acc[mt][j], ah[mt][0], ah[mt][1], ah[mt][2], ah[mt][3],
                             bh[j][0], bh[j][1]);
                    mma16816(acc[mt][j], al[mt][0], al[mt][1], al[mt][2], al[mt][3],
                             bh[j][0], bh[j][1]);
                    mma16816(acc[mt][j], ah[mt][0], ah[mt][1], ah[mt][2], ah[mt][3],
                             bl[j][0], bl[j][1]);
                }
            }
        }

        // ---- fused alpha epilogue (MODE 0) ----
        if (MODE == 0) {
            float sAS[2][2][2], sAD[2][2][2];
#pragma unroll
            for (int a = 0; a < 2; a++)
#pragma unroll
                for (int hf = 0; hf < 2; hf++)
#pragma unroll
                    for (int h = 0; h < 2; h++) { sAS[a][hf][h] = 0.f; sAD[a][hf][h] = 0.f; }
#pragma unroll
            for (int mt = 0; mt < 2; mt++)
#pragma unroll
                for (int j = 0; j < 4; j++) {
                    int hl = j >> 1;
                    int col = nb + j * 8 + 2 * cq;
                    float w0 = att[col], w1 = att[col + 1];
                    float u0 = att[128 + col], u1 = att[128 + col + 1];
                    sAS[mt][0][hl] += acc[mt][j][0] * w0 + acc[mt][j][1] * w1;
                    sAS[mt][1][hl] += acc[mt][j][2] * w0 + acc[mt][j][3] * w1;
                    sAD[mt][0][hl] += acc[mt][j][0] * u0 + acc[mt][j][1] * u1;
                    sAD[mt][1][hl] += acc[mt][j][2] * u0 + acc[mt][j][3] * u1;
                }
#pragma unroll
            for (int mt = 0; mt < 2; mt++)
#pragma unroll
                for (int hf = 0; hf < 2; hf++)
#pragma unroll
                    for (int h = 0; h < 2; h++) {
                        float v = sAS[mt][hf][h];
                        v += __shfl_xor_sync(0xffffffffu, v, 1);
                        v += __shfl_xor_sync(0xffffffffu, v, 2);
                        sAS[mt][hf][h] = v;
                        float u = sAD[mt][hf][h];
                        u += __shfl_xor_sync(0xffffffffu, u, 1);
                        u += __shfl_xor_sync(0xffffffffu, u, 2);
                        sAD[mt][hf][h] = u;
                    }
            if (cq == 0) {
#pragma unroll
                for (int mt = 0; mt < 2; mt++)
#pragma unroll
                    for (int hf = 0; hf < 2; hf++) {
                        int r = m0 + mb + mt * 16 + hf * 8 + gq;
                        if (r < M) {
                            __half2 p = __floats2half2_rn(sAS[mt][hf][0], sAS[mt][hf][1]);
                            *(uint32_t*)(oAS + (size_t)r * 8 + (nb >> 4)) =
                                *reinterpret_cast<uint32_t*>(&p);
                            *(float2*)(oAD + (size_t)r * 8 + (nb >> 4)) =
                                make_float2(sAD[mt][hf][0], sAD[mt][hf][1]);
                        }
                    }
            }
        }

        // ---- stage C in SMEM (overlaps A region; B untouched) ----
        __syncthreads();
#pragma unroll
        for (int mt = 0; mt < 2; mt++)
#pragma unroll
            for (int j = 0; j < 4; j++) {
                int row = mb + mt * 16 + gq;
                int col = nb + j * 8 + 2 * cq;
                *(float2*)(Cs + row * 132 + col) = make_float2(acc[mt][j][0], acc[mt][j][1]);
                *(float2*)(Cs + (row + 8) * 132 + col) = make_float2(acc[mt][j][2], acc[mt][j][3]);
            }
        __syncthreads();

        if (MODE == 0) {
#pragma unroll
            for (int it = 0; it < 8; it++) {
                int q = tid + it * 256;
                int r = q >> 5, w = q & 31;
                int m = m0 + r;
                if (m < M) {
                    float4 v = *(float4*)(Cs + r * 132 + w * 4);
                    __half2 p0 = __floats2half2_rn(v.x, v.y);
                    __half2 p1 = __floats2half2_rn(v.z, v.w);
                    uint2 u;
                    u.x = *reinterpret_cast<uint32_t*>(&p0);
                    u.y = *reinterpret_cast<uint32_t*>(&p1);
                    *(uint2*)(Ch + (size_t)m * HID + w * 4) = u;
                }
            }
        } else {
            // fused output head: out[m] = relu( relu(C[m]+b1) @ W2 + b2 ), OUT_DIM=3
            int r = tid >> 2;
            int qq = tid & 3;
            int m = m0 + r;
            float p0 = 0.f, p1 = 0.f, p2 = 0.f;
            const float* cr = Cs + r * 132 + qq * 32;
            const float* ar = att + qq * 32;
            const float* w2 = W2g + qq * 32 * 3;
#pragma unroll
            for (int i = 0; i < 32; i++) {
                float v = fmaxf(cr[i] + ar[i], 0.f);
                p0 = fmaf(v, __ldg(&w2[i * 3 + 0]), p0);
                p1 = fmaf(v, __ldg(&w2[i * 3 + 1]), p1);
                p2 = fmaf(v, __ldg(&w2[i * 3 + 2]), p2);
            }
            p0 += __shfl_xor_sync(0xffffffffu, p0, 1);
            p0 += __shfl_xor_sync(0xffffffffu, p0, 2);
            p1 += __shfl_xor_sync(0xffffffffu, p1, 1);
            p1 += __shfl_xor_sync(0xffffffffu, p1, 2);
            p2 += __shfl_xor_sync(0xffffffffu, p2, 1);
            p2 += __shfl_xor_sync(0xffffffffu, p2, 2);
            if (qq == 0 && m < M) {
                outg[(size_t)m * 3 + 0] = fmaxf(p0 + __ldg(&b2g[0]), 0.f);
                outg[(size_t)m * 3 + 1] = fmaxf(p1 + __ldg(&b2g[1]), 0.f);
                outg[(size_t)m * 3 + 2] = fmaxf(p2 + __ldg(&b2g[2]), 0.f);
            }
        }
        __syncthreads();  // Cs readback done before next iteration's A fill
    }
}

// ---------------- fused attention + aggregation + residual + LN (R7 champion) ----
// Half-warp per edge; each lane covers 8 channels; 1-ahead (src,ea) prefetch.
// 64-thread blocks: finest retirement granularity without occupancy loss.
__global__ void k_gat_edge(const float* __restrict__ hcur, const float* __restrict__ weh_l,
                           const float* __restrict__ bgl, const float* __restrict__ lng,
                           const float* __restrict__ lnb, float* __restrict__ hnext, int Nn) {
    int gw = (blockIdx.x * blockDim.x + threadIdx.x) >> 5;
    if (gw >= Nn) return;
    int lane = threadIdx.x & 31;
    int half = lane >> 4;
    int sl = lane & 15;      // channel group: 8*sl .. 8*sl+7
    int hh = sl >> 1;        // head
    float adv = __ldg(&g_ad[(size_t)gw * 8 + hh]);
    float w0 = __ldg(&weh_l[0 * 8 + hh]);
    float w1 = __ldg(&weh_l[1 * 8 + hh]);
    float w2 = __ldg(&weh_l[2 * 8 + hh]);
    float w3 = __ldg(&weh_l[3 * 8 + hh]);
    int s0 = g_off[gw], s1 = g_off[gw + 1];
    int d = s1 - s0;

    float acc[8];
#pragma unroll
    for (int q = 0; q < 8; q++) acc[q] = 0.f;
    float den = 0.f;

    int i = half;
    int sP = 0; uint2 eaP = make_uint2(0, 0);
    if (i < d) { sP = __ldg(&g_srcS[s0 + i]); eaP = g_eaS2[s0 + i]; }
    for (; i < d; i += 2) {
        int s = sP; uint2 eau = eaP;
        if (i + 2 < d) { sP = __ldg(&g_srcS[s0 + i + 2]); eaP = g_eaS2[s0 + i + 2]; }
        float asv = __half2float(g_as16[(size_t)s * 8 + hh]);
        float2 f01 = __half22float2(*reinterpret_cast<__half2*>(&eau.x));
        float2 f23 = __half22float2(*reinterpret_cast<__half2*>(&eau.y));
        float al = asv + adv + f01.x * w0 + f01.y * w1 + f23.x * w2 + f23.y * w3;
        al = fmaxf(al, 0.2f * al);
        float a = ex2(al);
        den += a;
        uint4 hv = *(const uint4*)(g_hp16 + (size_t)s * HID + sl * 8);
        __half2* hp2 = reinterpret_cast<__half2*>(&hv);
#pragma unroll
        for (int q = 0; q < 4; q++) {
            float2 f = __half22float2(hp2[q]);
            acc[2 * q] = fmaf(a, f.x, acc[2 * q]);
            acc[2 * q + 1] = fmaf(a, f.y, acc[2 * q + 1]);
        }
    }

    // merge even/odd halves (fixed order)
#pragma unroll
    for (int q = 0; q < 8; q++) acc[q] += __shfl_xor_sync(0xffffffffu, acc[q], 16);
    den += __shfl_xor_sync(0xffffffffu, den, 16);

    float r = 1.f / (den + 1e-16f);
    const float4* hcr = (const float4*)(hcur + (size_t)gw * HID + sl * 8);
    float4 hc0 = hcr[0], hc1 = hcr[1];
    const float4* bgr = (const float4*)(bgl + sl * 8);
    float4 bg0 = bgr[0], bg1 = bgr[1];
    float t8[8];
    t8[0] = hc0.x + acc[0] * r + bg0.x;
    t8[1] = hc0.y + acc[1] * r + bg0.y;
    t8[2] = hc0.z + acc[2] * r + bg0.z;
    t8[3] = hc0.w + acc[3] * r + bg0.w;
    t8[4] = hc1.x + acc[4] * r + bg1.x;
    t8[5] = hc1.y + acc[5] * r + bg1.y;
    t8[6] = hc1.z + acc[6] * r + bg1.z;
    t8[7] = hc1.w + acc[7] * r + bg1.w;
    float sm = 0.f, sq = 0.f;
#pragma unroll
    for (int q = 0; q < 8; q++) { sm += t8[q]; sq += t8[q] * t8[q]; }
    sm = warp_sum(sm);  // both halves duplicate -> 2x channel sum
    sq = warp_sum(sq);
    float mu = sm * (1.f / 256.f);
    float var = sq * (1.f / 256.f) - mu * mu;
    float rs = rsqrtf(var + 1e-5f);
    if (half == 0) {
        const float4* gr = (const float4*)(lng + sl * 8);
        const float4* br = (const float4*)(lnb + sl * 8);
        float4 g0 = gr[0], g1 = gr[1];
        float4 b0 = br[0], b1 = br[1];
        float4 o0, o1;
        o0.x = (t8[0] - mu) * rs * g0.x + b0.x;
        o0.y = (t8[1] - mu) * rs * g0.y + b0.y;
        o0.z = (t8[2] - mu) * rs * g0.z + b0.z;
        o0.w = (t8[3] - mu) * rs * g0.w + b0.w;
        o1.x = (t8[4] - mu) * rs * g1.x + b1.x;
        o1.y = (t8[5] - mu) * rs * g1.y + b1.y;
        o1.z = (t8[6] - mu) * rs * g1.z + b1.z;
        o1.w = (t8[7] - mu) * rs * g1.w + b1.w;
        float4* outp = (float4*)(hnext + (size_t)gw * HID + sl * 8);
        outp[0] = o0;
        outp[1] = o1;
    }
}

// ---------------- launch ----------------
extern "C" void kernel_launch(void* const* d_in, const int* in_sizes, int n_in,
                              void* d_out, int out_size) {
    const float* x = (const float*)d_in[0];
    const int* ei = (const int*)d_in[1];
    const float* ea = (const float*)d_in[2];
    const float* W_in = (const float*)d_in[3];
    const float* b_in = (const float*)d_in[4];
    const float* ln_in_g = (const float*)d_in[5];
    const float* ln_in_b = (const float*)d_in[6];
    const float* Wg = (const float*)d_in[7];
    const float* att_src = (const float*)d_in[8];
    const float* att_dst = (const float*)d_in[9];
    const float* We = (const float*)d_in[10];
    const float* att_edge = (const float*)d_in[11];
    const float* bg = (const float*)d_in[12];
    const float* ln_g = (const float*)d_in[13];
    const float* ln_b = (const float*)d_in[14];
    const float* W1 = (const float*)d_in[15];
    const float* b1 = (const float*)d_in[16];
    const float* W2 = (const float*)d_in[17];
    const float* b2 = (const float*)d_in[18];

    int Nn = in_sizes[0] / 16;   // 100000
    int Ee = in_sizes[2] / 4;    // 1600000

    float *hA, *hB, *weh, *ad;
    __half *hp16, *as16;
    __nv_bfloat16 *Bh, *Bl;
    cudaGetSymbolAddress((void**)&hA, g_hA);
    cudaGetSymbolAddress((void**)&hB, g_hB);
    cudaGetSymbolAddress((void**)&hp16, g_hp16);
    cudaGetSymbolAddress((void**)&weh, g_weh);
    cudaGetSymbolAddress((void**)&as16, g_as16);
    cudaGetSymbolAddress((void**)&ad, g_ad);
    cudaGetSymbolAddress((void**)&Bh, g_Bh);
    cudaGetSymbolAddress((void**)&Bl, g_Bl);

    cudaFuncSetAttribute(k_mma<0>, cudaFuncAttributeMaxDynamicSharedMemorySize, SM_TOT);
    cudaFuncSetAttribute(k_mma<1>, cudaFuncAttributeMaxDynamicSharedMemorySize, SM_TOT);

    int nwb = (Nn + 7) / 8;       // 256-thread blocks (input proj)
    int neb = (Nn + 1) / 2;       // 64-thread blocks (edge kernel)

    // ---- independent prep first, layer-0 GEMM at launch position 4 (ncu target) ----
    k_prep_bsplit<<<NLAYERS + 1, 128>>>(Wg, W1);                               // 1
    k_input<<<nwb, 256>>>(x, W_in, b_in, ln_in_g, ln_in_b, hA, Nn);            // 2
    k_prep_weh<<<NLAYERS, 32>>>(We, att_edge);                                 // 3
    k_mma<0><<<GEMM_GRID, 256, SM_TOT>>>(hA, Bh, Bl, att_src, att_dst,         // 4 <- ncu target
                                         hp16, as16, ad, nullptr, nullptr, nullptr, Nn);

    // ---- CSR preprocessing ----
    k_zero<<<(Nn + 255) / 256, 256>>>(Nn);
    k_hist<<<(Ee + 255) / 256, 256>>>(ei, Ee);
    int nb = (Nn + 1023) / 1024;
    k_scan1<<<nb, 1024>>>(Nn);
    k_scan2<<<1, 32>>>(nb);
    k_scan3<<<nb, 1024>>>(Nn);
    k_scatter<<<(Ee + 255) / 256, 256>>>(ei, Ee);
    k_sortfix<<<(Nn + 255) / 256, 256>>>(ei, (const float4*)ea, Nn);

    // ---- GAT layers (layer 0 GEMM already done) ----
    float* hcur = hA;
    float* hnxt = hB;
    for (int l = 0; l < NLAYERS; l++) {
        if (l > 0) {
            k_mma<0><<<GEMM_GRID, 256, SM_TOT>>>(hcur, Bh + (size_t)l * HID * HID,
                                                 Bl + (size_t)l * HID * HID,
                                                 att_src + l * HID, att_dst + l * HID,
                                                 hp16, as16, ad, nullptr, nullptr, nullptr, Nn);
        }
        k_gat_edge<<<neb, 64>>>(hcur, weh + l * 32, bg + l * HID,
                                ln_g + l * HID, ln_b + l * HID, hnxt, Nn);
        float* t = hcur; hcur = hnxt; hnxt = t;
    }

    // ---- output head (fully fused into k_mma<1>) ----
    k_mma<1><<<GEMM_GRID, 256, SM_TOT>>>(hcur, Bh + (size_t)NLAYERS * HID * HID,
                                         Bl + (size_t)NLAYERS * HID * HID,
                                         b1, b1, nullptr, nullptr, nullptr,
                                         W2, b2, (float*)d_out, Nn);
}